// round 7
// baseline (speedup 1.0000x reference)
#include <cuda_runtime.h>
#include <cuda_bf16.h>
#include <cstdint>
#include <cstddef>

// ---------------------------------------------------------------------------
// DependencyParsingNetwork: embed -> 2-layer biLSTM (T=2048, H=256) -> masked
// tanh score matrix [T,T].
//
//   1. gemm_bias2: pre0{f,b} = gather(E,idx) @ Wih0{f,b}^T + b    (one launch)
//   2. lstm_layer: cluster of 16 CTAs per direction (nonportable size);
//      h exchanged via 64B cp.async.bulk cluster copies issued in parallel
//      by warp-0 lanes with loop-invariant precomputed mapa addresses.
//   3. gemm_bias2: pre1{f,b} = x1 @ Wih1{f,b}^T + b
//   4. lstm_layer -> x2
//   5. heads + masked tanh scores
// ---------------------------------------------------------------------------

#define TLEN 2048
#define HID  256
#define CSZ  16     // cluster size (CTAs per direction)

// ------------------------- device scratch (static) -------------------------
__device__ float g_pre0f[TLEN * 1024];
__device__ float g_pre0b[TLEN * 1024];
__device__ float g_pre1f[TLEN * 1024];
__device__ float g_pre1b[TLEN * 1024];
__device__ float g_x1[TLEN * 512];
__device__ float g_x2[TLEN * 512];
__device__ float g_sh[TLEN];
__device__ float g_sd[TLEN];

// ------------------------------ helpers ------------------------------------
__device__ __forceinline__ uint32_t smem_u32(const void* p) {
    uint32_t a;
    asm("{ .reg .u64 t; cvta.to.shared.u64 t, %1; cvt.u32.u64 %0, t; }"
        : "=r"(a) : "l"(p));
    return a;
}

#define CLUSTER_SYNC() do { \
    asm volatile("barrier.cluster.arrive.aligned;" ::: "memory"); \
    asm volatile("barrier.cluster.wait.aligned;" ::: "memory"); \
} while (0)

__device__ __forceinline__ void mbar_init(uint32_t mbar, uint32_t count) {
    asm volatile("mbarrier.init.shared.b64 [%0], %1;" :: "r"(mbar), "r"(count)
                 : "memory");
}
__device__ __forceinline__ void mbar_expect_tx(uint32_t mbar, uint32_t bytes) {
    asm volatile("mbarrier.arrive.expect_tx.shared.b64 _, [%0], %1;"
                 :: "r"(mbar), "r"(bytes) : "memory");
}
// acquire at cluster scope: data was produced by remote-CTA bulk copies
__device__ __forceinline__ void mbar_wait_cluster(uint32_t mbar, uint32_t parity) {
    uint32_t done;
    asm volatile(
        "{\n\t.reg .pred p;\n\t"
        "mbarrier.try_wait.parity.acquire.cluster.shared::cta.b64 p, [%1], %2;\n\t"
        "selp.b32 %0, 1, 0, p;\n\t}"
        : "=r"(done) : "r"(mbar), "r"(parity) : "memory");
    while (!done) {
        asm volatile(
            "{\n\t.reg .pred p;\n\t"
            "mbarrier.try_wait.parity.acquire.cluster.shared::cta.b64 p, [%1], %2, 0x989680;\n\t"
            "selp.b32 %0, 1, 0, p;\n\t}"
            : "=r"(done) : "r"(mbar), "r"(parity) : "memory");
    }
}
__device__ __forceinline__ uint32_t mapa_u32(uint32_t laddr, uint32_t rank) {
    uint32_t r;
    asm volatile("mapa.shared::cluster.u32 %0, %1, %2;"
                 : "=r"(r) : "r"(laddr), "r"(rank));
    return r;
}
// bulk copy local smem -> (possibly remote) cluster smem, complete_tx on the
// destination CTA's mbarrier.
__device__ __forceinline__ void bulk_s2s(uint32_t dst, uint32_t src,
                                         uint32_t bytes, uint32_t rmbar) {
    asm volatile(
        "cp.async.bulk.shared::cluster.shared::cta.mbarrier::complete_tx::bytes "
        "[%0], [%1], %2, [%3];"
        :: "r"(dst), "r"(src), "r"(bytes), "r"(rmbar) : "memory");
}

__device__ __forceinline__ float sigmoidf_(float x) {
    float e = __expf(-fabsf(x));
    float s = __fdividef(1.f, 1.f + e);
    return x >= 0.f ? s : 1.f - s;
}
__device__ __forceinline__ float tanhf_(float x) {
    float e = __expf(-2.f * fabsf(x));
    float t = __fdividef(1.f - e, 1.f + e);
    return x >= 0.f ? t : -t;
}

// ------------------------------ GEMM ---------------------------------------
// out{0,1}[M,N] = A[M,K] @ W{0,1}[N,K]^T + bias{0,1}[N]; z selects direction.
#define BM 64
#define BN 64
#define BK 16

__global__ __launch_bounds__(256) void gemm_bias2_kernel(
    const float* __restrict__ X, const int* __restrict__ idx,
    const float* __restrict__ E,
    const float* __restrict__ W0, const float* __restrict__ bias0,
    float* __restrict__ out0,
    const float* __restrict__ W1, const float* __restrict__ bias1,
    float* __restrict__ out1,
    int M, int N, int K)
{
    __shared__ __align__(16) float As[BK][BM + 4];
    __shared__ __align__(16) float Bs[BK][BN + 4];

    const float* W    = blockIdx.z ? W1    : W0;
    const float* bias = blockIdx.z ? bias1 : bias0;
    float*       out  = blockIdx.z ? out1  : out0;

    int tid = threadIdx.x;
    int m0 = blockIdx.y * BM, n0 = blockIdx.x * BN;
    int lrow = tid >> 2;          // 0..63
    int lcol = (tid & 3) * 4;     // 0,4,8,12
    int tx = tid & 15, ty = tid >> 4;

    float acc[4][4] = {};

    const float* Arow;
    if (idx) Arow = E + (size_t)idx[m0 + lrow] * K;
    else     Arow = X + (size_t)(m0 + lrow) * K;
    const float* Brow = W + (size_t)(n0 + lrow) * K;

    for (int k0 = 0; k0 < K; k0 += BK) {
        float4 av = *(const float4*)(Arow + k0 + lcol);
        float4 bv = *(const float4*)(Brow + k0 + lcol);
        As[lcol + 0][lrow] = av.x; As[lcol + 1][lrow] = av.y;
        As[lcol + 2][lrow] = av.z; As[lcol + 3][lrow] = av.w;
        Bs[lcol + 0][lrow] = bv.x; Bs[lcol + 1][lrow] = bv.y;
        Bs[lcol + 2][lrow] = bv.z; Bs[lcol + 3][lrow] = bv.w;
        __syncthreads();

        #pragma unroll
        for (int kk = 0; kk < BK; kk++) {
            float4 a = *(const float4*)&As[kk][ty * 4];
            float4 b = *(const float4*)&Bs[kk][tx * 4];
            acc[0][0] += a.x * b.x; acc[0][1] += a.x * b.y;
            acc[0][2] += a.x * b.z; acc[0][3] += a.x * b.w;
            acc[1][0] += a.y * b.x; acc[1][1] += a.y * b.y;
            acc[1][2] += a.y * b.z; acc[1][3] += a.y * b.w;
            acc[2][0] += a.z * b.x; acc[2][1] += a.z * b.y;
            acc[2][2] += a.z * b.z; acc[2][3] += a.z * b.w;
            acc[3][0] += a.w * b.x; acc[3][1] += a.w * b.y;
            acc[3][2] += a.w * b.z; acc[3][3] += a.w * b.w;
        }
        __syncthreads();
    }

    #pragma unroll
    for (int i = 0; i < 4; i++) {
        int m = m0 + ty * 4 + i;
        #pragma unroll
        for (int jj = 0; jj < 4; jj++) {
            int n = n0 + tx * 4 + jj;
            out[(size_t)m * N + n] = acc[i][jj] + bias[n];
        }
    }
}

// --------------------------- LSTM recurrence --------------------------------
// Cluster of CSZ=16 CTAs per direction (runtime cluster dims, nonportable).
// Thread map: tid = unit*16 + gate*4 + quarter (16 units, 4 gates, 4 K-quarters
// of 64). Each 16-lane group owns one hidden unit. Dot = 64 FMA/thread,
// width-4 shuffle reduce, width-16 gate gather, redundant activations.
// h slice (16 floats = 64B) exchanged via per-lane cp.async.bulk with
// loop-invariant precomputed mapa addresses.
__global__ void __launch_bounds__(256, 1)
lstm_layer_kernel(const float* __restrict__ pre_f, const float* __restrict__ pre_b,
                  const float* __restrict__ Whh_f, const float* __restrict__ Whh_b,
                  float* __restrict__ out, int ostride)
{
    __shared__ __align__(16) float hbuf[2][HID];
    __shared__ __align__(16) float stage[2][16];
    __shared__ __align__(8)  uint64_t mbar_store[2];

    int tid  = threadIdx.x;
    uint32_t rank;
    asm("mov.u32 %0, %%cluster_ctarank;" : "=r"(rank));
    int dir  = (blockIdx.x >= CSZ) ? 1 : 0;

    const float* pre = dir ? pre_b : pre_f;
    const float* Whh = dir ? Whh_b : Whh_f;
    int off = dir ? HID : 0;

    int unit    = tid >> 4;              // 0..15 local unit
    int k       = tid & 15;              // lane within unit group
    int gate    = k >> 2;                // 0..3 (i,f,g,o)
    int quarter = k & 3;                 // K quarter (64 elements)
    int gr   = gate * HID + (int)rank * 16 + unit;  // gate row (0..1023)
    int u    = (int)rank * 16 + unit;               // global hidden unit

    uint32_t mb_base = smem_u32(&mbar_store[0]);
    uint32_t hb      = smem_u32(&hbuf[0][0]);
    uint32_t stg     = smem_u32(&stage[0][0]);

    // load this thread's 64 Whh weights into registers
    float4 w4[16];
    const float4* wsrc = (const float4*)(Whh + (size_t)gr * HID + quarter * 64);
    #pragma unroll
    for (int i = 0; i < 16; i++) w4[i] = wsrc[i];

    // loop-invariant remote addresses: lane r (of warp 0) pushes to rank r
    uint32_t lane_rank = (uint32_t)(tid & 15);
    uint32_t r_dst0 = mapa_u32(hb + rank * 64u,          lane_rank);
    uint32_t r_dst1 = mapa_u32(hb + 1024u + rank * 64u,  lane_rank);
    uint32_t r_mb0  = mapa_u32(mb_base,       lane_rank);
    uint32_t r_mb1  = mapa_u32(mb_base + 8u,  lane_rank);

    // init: zero BOTH parity buffers (t=0 reads hbuf[1] as h(-1))
    hbuf[0][tid] = 0.f;
    hbuf[1][tid] = 0.f;
    if (tid < 2) mbar_init(mb_base + tid * 8u, 1);
    __syncthreads();
    if (tid == 0) mbar_expect_tx(mb_base, HID * 4);   // expect h(0): 1024B
    CLUSTER_SYNC();                      // inits + expect visible cluster-wide

    float c = 0.f;
    int tt0 = dir ? (TLEN - 1) : 0;
    float pv = __ldg(&pre[tt0 * 1024 + gr]);      // prefetch for t = 0

    for (int t = 0; t < TLEN; t++) {
        if (t > 0) {
            int tm = t - 1;   // wait h(t-1): mbar[tm&1], parity (tm>>1)&1
            mbar_wait_cluster(mb_base + (uint32_t)(tm & 1) * 8u,
                              (uint32_t)((tm >> 1) & 1));
        }

        // prefetch pre for t+1 (hidden under the dot)
        float pv_next = 0.f;
        if (t + 1 < TLEN) {
            int tt1 = dir ? (TLEN - 2 - t) : (t + 1);
            pv_next = __ldg(&pre[tt1 * 1024 + gr]);
        }

        int q  = t & 1;        // buffer receiving h(t)
        int qp = q ^ 1;        // buffer holding h(t-1)

        const float4* h4 = (const float4*)&hbuf[qp][quarter * 64];
        float ax = 0.f, ay = 0.f, az = 0.f, aw = 0.f;
        #pragma unroll
        for (int i = 0; i < 16; i++) {
            float4 hv = h4[i];
            ax += w4[i].x * hv.x; ay += w4[i].y * hv.y;
            az += w4[i].z * hv.z; aw += w4[i].w * hv.w;
        }
        float dot = (ax + ay) + (az + aw);
        dot += __shfl_xor_sync(0xffffffffu, dot, 1);   // combine quarters
        dot += __shfl_xor_sync(0xffffffffu, dot, 2);
        dot += pv;                                     // + input projection

        // gather the 4 gates of this unit into all 16 group lanes
        float gi = __shfl_sync(0xffffffffu, dot,  0, 16);
        float gf = __shfl_sync(0xffffffffu, dot,  4, 16);
        float gg = __shfl_sync(0xffffffffu, dot,  8, 16);
        float go = __shfl_sync(0xffffffffu, dot, 12, 16);

        // redundant (deterministic) activation in all 16 lanes
        c = sigmoidf_(gf) * c + sigmoidf_(gi) * tanhf_(gg);
        float h = sigmoidf_(go) * tanhf_(c);

        int tt = dir ? (TLEN - 1 - t) : t;
        if (k == 0) {
            out[(size_t)tt * ostride + off + u] = h;
            stage[q][unit] = h;            // local staging for bulk copy
        }
        // post expect for h(t+1); ordered before our h(t) bulks by the sync
        if (t + 1 < TLEN && tid == 0)
            mbar_expect_tx(mb_base + (uint32_t)((t + 1) & 1) * 8u, HID * 4);

        // one barrier per step: staging complete + expect posted + hbuf[qp]
        // reads done (WAR protection against early h(t+1) arrivals)
        __syncthreads();

        // warp-0 lanes 0..15 each push our 64B slice to one destination CTA
        if (t + 1 < TLEN && tid < CSZ) {
            asm volatile("fence.proxy.async.shared::cta;" ::: "memory");
            uint32_t src = stg + (uint32_t)q * 64u;
            bulk_s2s(q ? r_dst1 : r_dst0, src, 64u, q ? r_mb1 : r_mb0);
        }
        pv = pv_next;
    }
    CLUSTER_SYNC();   // no CTA exits with an in-flight bulk copy
}

// ------------------------------ heads --------------------------------------
__global__ __launch_bounds__(256) void heads_kernel(
    const float* __restrict__ x2, const float* __restrict__ Wm,
    float* __restrict__ sh, float* __restrict__ sd)
{
    int warp = threadIdx.x >> 5, lane = threadIdx.x & 31;
    int row = blockIdx.x * 8 + warp;
    const float4* xr = (const float4*)(x2 + (size_t)row * 512);
    const float4* wh = (const float4*)(Wm);
    const float4* wd = (const float4*)(Wm + 512);
    float a = 0.f, b = 0.f;
    #pragma unroll 4
    for (int i = lane; i < 128; i += 32) {
        float4 xv = xr[i]; float4 hv = wh[i]; float4 dv = wd[i];
        a += xv.x * hv.x + xv.y * hv.y + xv.z * hv.z + xv.w * hv.w;
        b += xv.x * dv.x + xv.y * dv.y + xv.z * dv.z + xv.w * dv.w;
    }
    #pragma unroll
    for (int o = 16; o; o >>= 1) {
        a += __shfl_xor_sync(0xffffffffu, a, o);
        b += __shfl_xor_sync(0xffffffffu, b, o);
    }
    if (lane == 0) { sh[row] = a; sd[row] = b; }
}

// ------------------------------ scores -------------------------------------
__global__ __launch_bounds__(256) void scores_kernel(
    const float* __restrict__ sh, const float* __restrict__ sd,
    const float* __restrict__ bm, float* __restrict__ out)
{
    float bb = __ldg(bm);
    size_t nquad = (size_t)TLEN * TLEN / 4;
    size_t stride = (size_t)gridDim.x * blockDim.x;
    for (size_t idx = (size_t)blockIdx.x * blockDim.x + threadIdx.x;
         idx < nquad; idx += stride) {
        int i  = (int)(idx >> 9);           // row (2048/4 = 512 quads per row)
        int j0 = (int)((idx & 511) << 2);   // first col of quad
        float si = sh[i];
        float4 r;
        r.x = (j0 + 0 > i) ? tanhf(si + sd[j0 + 0] + bb) : 0.f;
        r.y = (j0 + 1 > i) ? tanhf(si + sd[j0 + 1] + bb) : 0.f;
        r.z = (j0 + 2 > i) ? tanhf(si + sd[j0 + 2] + bb) : 0.f;
        r.w = (j0 + 3 > i) ? tanhf(si + sd[j0 + 3] + bb) : 0.f;
        *(float4*)(out + ((size_t)i * TLEN + j0)) = r;
    }
}

// ------------------------------ launch -------------------------------------
static void launch_lstm(const float* pf, const float* pb,
                        const float* wf, const float* wb,
                        float* out, int ostride)
{
    static int attr_set = 0;
    if (!attr_set) {
        cudaFuncSetAttribute(lstm_layer_kernel,
                             cudaFuncAttributeNonPortableClusterSizeAllowed, 1);
        attr_set = 1;
    }
    cudaLaunchConfig_t cfg = {};
    cfg.gridDim  = dim3(2 * CSZ, 1, 1);
    cfg.blockDim = dim3(256, 1, 1);
    cudaLaunchAttribute at[1];
    at[0].id = cudaLaunchAttributeClusterDimension;
    at[0].val.clusterDim.x = CSZ;
    at[0].val.clusterDim.y = 1;
    at[0].val.clusterDim.z = 1;
    cfg.attrs = at;
    cfg.numAttrs = 1;
    cudaLaunchKernelEx(&cfg, lstm_layer_kernel, pf, pb, wf, wb, out, ostride);
}

extern "C" void kernel_launch(void* const* d_in, const int* in_sizes, int n_in,
                              void* d_out, int out_size)
{
    const int*   word_idx = (const int*)  d_in[0];
    const float* E        = (const float*)d_in[1];
    const float* Wih0f    = (const float*)d_in[2];
    const float* Whh0f    = (const float*)d_in[3];
    const float* b0f      = (const float*)d_in[4];
    const float* Wih0b    = (const float*)d_in[5];
    const float* Whh0b    = (const float*)d_in[6];
    const float* b0b      = (const float*)d_in[7];
    const float* Wih1f    = (const float*)d_in[8];
    const float* Whh1f    = (const float*)d_in[9];
    const float* b1f      = (const float*)d_in[10];
    const float* Wih1b    = (const float*)d_in[11];
    const float* Whh1b    = (const float*)d_in[12];
    const float* b1b      = (const float*)d_in[13];
    const float* Wm       = (const float*)d_in[14];
    const float* bm       = (const float*)d_in[15];
    float* out = (float*)d_out;

    float *pre0f, *pre0b, *pre1f, *pre1b, *x1, *x2, *sh, *sd;
    cudaGetSymbolAddress((void**)&pre0f, g_pre0f);
    cudaGetSymbolAddress((void**)&pre0b, g_pre0b);
    cudaGetSymbolAddress((void**)&pre1f, g_pre1f);
    cudaGetSymbolAddress((void**)&pre1b, g_pre1b);
    cudaGetSymbolAddress((void**)&x1,    g_x1);
    cudaGetSymbolAddress((void**)&x2,    g_x2);
    cudaGetSymbolAddress((void**)&sh,    g_sh);
    cudaGetSymbolAddress((void**)&sd,    g_sd);

    dim3 gg(1024 / BN, TLEN / BM, 2);

    // layer 0 input projection (both directions, fused embedding gather)
    gemm_bias2_kernel<<<gg, 256>>>(nullptr, word_idx, E,
                                   Wih0f, b0f, pre0f, Wih0b, b0b, pre0b,
                                   TLEN, 1024, 256);
    // layer 0 recurrence (fwd + bwd clusters)
    launch_lstm(pre0f, pre0b, Whh0f, Whh0b, x1, 512);

    // layer 1 input projection
    gemm_bias2_kernel<<<gg, 256>>>(x1, nullptr, nullptr,
                                   Wih1f, b1f, pre1f, Wih1b, b1b, pre1b,
                                   TLEN, 1024, 512);
    // layer 1 recurrence
    launch_lstm(pre1f, pre1b, Whh1f, Whh1b, x2, 512);

    // scoring head
    heads_kernel<<<TLEN / 8, 256>>>(x2, Wm, sh, sd);
    scores_kernel<<<2048, 256>>>(sh, sd, bm, out);
}

// round 10
// speedup vs baseline: 1.9358x; 1.9358x over previous
#include <cuda_runtime.h>
#include <cuda_bf16.h>
#include <cstdint>
#include <cstddef>

// ---------------------------------------------------------------------------
// DependencyParsingNetwork: embed -> 2-layer biLSTM (T=2048, H=256) -> masked
// tanh score matrix [T,T].
//
//   1. gemm_bias2: pre0{f,b} = gather(E,idx) @ Wih0{f,b}^T + b    (one launch)
//   2. lstm_layer: cluster of 8 CTAs per direction; dot via packed
//      fma.rn.f32x2 (FFMA2); h exchanged via register-direct st.async +
//      mbarrier complete_tx; one low-skew __syncthreads right after the wait.
//   3. gemm_bias2: pre1{f,b} = x1 @ Wih1{f,b}^T + b
//   4. lstm_layer -> x2
//   5. heads + masked tanh scores
// ---------------------------------------------------------------------------

#define TLEN 2048
#define HID  256
#define CSZ  8      // cluster size (CTAs per direction)

// ------------------------- device scratch (static) -------------------------
__device__ float g_pre0f[TLEN * 1024];
__device__ float g_pre0b[TLEN * 1024];
__device__ float g_pre1f[TLEN * 1024];
__device__ float g_pre1b[TLEN * 1024];
__device__ float g_x1[TLEN * 512];
__device__ float g_x2[TLEN * 512];
__device__ float g_sh[TLEN];
__device__ float g_sd[TLEN];

// ------------------------------ helpers ------------------------------------
__device__ __forceinline__ uint32_t smem_u32(const void* p) {
    uint32_t a;
    asm("{ .reg .u64 t; cvta.to.shared.u64 t, %1; cvt.u32.u64 %0, t; }"
        : "=r"(a) : "l"(p));
    return a;
}

#define CLUSTER_SYNC() do { \
    asm volatile("barrier.cluster.arrive.aligned;" ::: "memory"); \
    asm volatile("barrier.cluster.wait.aligned;" ::: "memory"); \
} while (0)

__device__ __forceinline__ void mbar_init(uint32_t mbar, uint32_t count) {
    asm volatile("mbarrier.init.shared.b64 [%0], %1;" :: "r"(mbar), "r"(count)
                 : "memory");
}
__device__ __forceinline__ void mbar_expect_tx(uint32_t mbar, uint32_t bytes) {
    asm volatile("mbarrier.arrive.expect_tx.shared.b64 _, [%0], %1;"
                 :: "r"(mbar), "r"(bytes) : "memory");
}
// acquire at cluster scope: data was produced by remote-CTA st.async
__device__ __forceinline__ void mbar_wait_cluster(uint32_t mbar, uint32_t parity) {
    uint32_t done;
    asm volatile(
        "{\n\t.reg .pred p;\n\t"
        "mbarrier.try_wait.parity.acquire.cluster.shared::cta.b64 p, [%1], %2;\n\t"
        "selp.b32 %0, 1, 0, p;\n\t}"
        : "=r"(done) : "r"(mbar), "r"(parity) : "memory");
    while (!done) {
        asm volatile(
            "{\n\t.reg .pred p;\n\t"
            "mbarrier.try_wait.parity.acquire.cluster.shared::cta.b64 p, [%1], %2, 0x989680;\n\t"
            "selp.b32 %0, 1, 0, p;\n\t}"
            : "=r"(done) : "r"(mbar), "r"(parity) : "memory");
    }
}
__device__ __forceinline__ uint32_t mapa_u32(uint32_t laddr, uint32_t rank) {
    uint32_t r;
    asm volatile("mapa.shared::cluster.u32 %0, %1, %2;"
                 : "=r"(r) : "r"(laddr), "r"(rank));
    return r;
}
// remote smem store with tx-count completion on remote mbarrier
__device__ __forceinline__ void st_async_f32(uint32_t raddr, float v, uint32_t rbar) {
    asm volatile(
        "st.async.shared::cluster.mbarrier::complete_tx::bytes.b32 [%0], %1, [%2];"
        :: "r"(raddr), "r"(__float_as_uint(v)), "r"(rbar) : "memory");
}

__device__ __forceinline__ float sigmoidf_(float x) {
    float e = __expf(-fabsf(x));
    float s = __fdividef(1.f, 1.f + e);
    return x >= 0.f ? s : 1.f - s;
}
__device__ __forceinline__ float tanhf_(float x) {
    float e = __expf(-2.f * fabsf(x));
    float t = __fdividef(1.f - e, 1.f + e);
    return x >= 0.f ? t : -t;
}

// ------------------------------ GEMM ---------------------------------------
// out{0,1}[M,N] = A[M,K] @ W{0,1}[N,K]^T + bias{0,1}[N]; z selects direction.
#define BM 64
#define BN 64
#define BK 16

__global__ __launch_bounds__(256) void gemm_bias2_kernel(
    const float* __restrict__ X, const int* __restrict__ idx,
    const float* __restrict__ E,
    const float* __restrict__ W0, const float* __restrict__ bias0,
    float* __restrict__ out0,
    const float* __restrict__ W1, const float* __restrict__ bias1,
    float* __restrict__ out1,
    int M, int N, int K)
{
    __shared__ __align__(16) float As[BK][BM + 4];
    __shared__ __align__(16) float Bs[BK][BN + 4];

    const float* W    = blockIdx.z ? W1    : W0;
    const float* bias = blockIdx.z ? bias1 : bias0;
    float*       out  = blockIdx.z ? out1  : out0;

    int tid = threadIdx.x;
    int m0 = blockIdx.y * BM, n0 = blockIdx.x * BN;
    int lrow = tid >> 2;          // 0..63
    int lcol = (tid & 3) * 4;     // 0,4,8,12
    int tx = tid & 15, ty = tid >> 4;

    float acc[4][4] = {};

    const float* Arow;
    if (idx) Arow = E + (size_t)idx[m0 + lrow] * K;
    else     Arow = X + (size_t)(m0 + lrow) * K;
    const float* Brow = W + (size_t)(n0 + lrow) * K;

    for (int k0 = 0; k0 < K; k0 += BK) {
        float4 av = *(const float4*)(Arow + k0 + lcol);
        float4 bv = *(const float4*)(Brow + k0 + lcol);
        As[lcol + 0][lrow] = av.x; As[lcol + 1][lrow] = av.y;
        As[lcol + 2][lrow] = av.z; As[lcol + 3][lrow] = av.w;
        Bs[lcol + 0][lrow] = bv.x; Bs[lcol + 1][lrow] = bv.y;
        Bs[lcol + 2][lrow] = bv.z; Bs[lcol + 3][lrow] = bv.w;
        __syncthreads();

        #pragma unroll
        for (int kk = 0; kk < BK; kk++) {
            float4 a = *(const float4*)&As[kk][ty * 4];
            float4 b = *(const float4*)&Bs[kk][tx * 4];
            acc[0][0] += a.x * b.x; acc[0][1] += a.x * b.y;
            acc[0][2] += a.x * b.z; acc[0][3] += a.x * b.w;
            acc[1][0] += a.y * b.x; acc[1][1] += a.y * b.y;
            acc[1][2] += a.y * b.z; acc[1][3] += a.y * b.w;
            acc[2][0] += a.z * b.x; acc[2][1] += a.z * b.y;
            acc[2][2] += a.z * b.z; acc[2][3] += a.z * b.w;
            acc[3][0] += a.w * b.x; acc[3][1] += a.w * b.y;
            acc[3][2] += a.w * b.z; acc[3][3] += a.w * b.w;
        }
        __syncthreads();
    }

    #pragma unroll
    for (int i = 0; i < 4; i++) {
        int m = m0 + ty * 4 + i;
        #pragma unroll
        for (int jj = 0; jj < 4; jj++) {
            int n = n0 + tx * 4 + jj;
            out[(size_t)m * N + n] = acc[i][jj] + bias[n];
        }
    }
}

// --------------------------- LSTM recurrence --------------------------------
// Thread map: tid = unit_local*8 + gate*2 + half  (32 units, 4 gates, 2 halves).
// Each 8-lane group owns one hidden unit. Dot = 64 packed fma.rn.f32x2 per
// thread (FFMA2), width-2 + width-8 shuffles for reduce/gather, redundant
// activations, register-direct st.async exchange.
__global__ void __cluster_dims__(CSZ, 1, 1) __launch_bounds__(256, 1)
lstm_layer_kernel(const float* __restrict__ pre_f, const float* __restrict__ pre_b,
                  const float* __restrict__ Whh_f, const float* __restrict__ Whh_b,
                  float* __restrict__ out, int ostride)
{
    __shared__ __align__(16) float hbuf[2][HID];
    __shared__ __align__(8)  uint64_t mbar_store[2];

    int tid  = threadIdx.x;
    int rank = blockIdx.x & (CSZ - 1);
    int dir  = blockIdx.x / CSZ;

    const float* pre = dir ? pre_b : pre_f;
    const float* Whh = dir ? Whh_b : Whh_f;
    int off = dir ? HID : 0;

    int unit = tid >> 3;                 // 0..31 local unit
    int k    = tid & 7;                  // lane within unit group
    int gate = k >> 1;                   // 0..3 (i,f,g,o)
    int half = k & 1;                    // K half
    int gr   = gate * HID + rank * 32 + unit;   // gate row (0..1023)
    int u    = rank * 32 + unit;                // global hidden unit

    uint32_t mb0 = smem_u32(&mbar_store[0]);
    uint32_t mb1 = smem_u32(&mbar_store[1]);
    uint32_t hb  = smem_u32(&hbuf[0][0]);

    // load this thread's 128 Whh weights as 32 x (2 packed f32x2)
    ulonglong2 w2[32];
    const ulonglong2* wsrc =
        (const ulonglong2*)(Whh + (size_t)gr * HID + half * 128);
    #pragma unroll
    for (int i = 0; i < 32; i++) w2[i] = wsrc[i];

    // remote addresses for my h pushes (to rank k), per parity
    uint32_t r_h0  = mapa_u32(hb + (uint32_t)u * 4u, (uint32_t)k);
    uint32_t r_h1  = r_h0 + (uint32_t)HID * 4u;
    uint32_t r_mb0 = mapa_u32(mb0, (uint32_t)k);
    uint32_t r_mb1 = r_mb0 + 8u;

    // init: zero BOTH parity buffers (t=0 reads hbuf[1] as h(-1))
    hbuf[0][tid] = 0.f;
    hbuf[1][tid] = 0.f;
    if (tid < 2) mbar_init(tid ? mb1 : mb0, 1);
    __syncthreads();
    if (tid == 0) mbar_expect_tx(mb0, HID * 4);   // expect h(0): 1024B
    CLUSTER_SYNC();                      // inits + expect visible cluster-wide

    float c = 0.f;
    int tt0 = dir ? (TLEN - 1) : 0;
    float pv = __ldg(&pre[tt0 * 1024 + gr]);      // prefetch for t = 0

    for (int t = 0; t < TLEN; t++) {
        if (t > 0) {
            int tm = t - 1;   // wait h(t-1): mbar[tm&1], parity (tm>>1)&1
            mbar_wait_cluster(tm & 1 ? mb1 : mb0, (uint32_t)((tm >> 1) & 1));
        }
        // re-arm: expect h(t+1) on mbar[(t+1)&1] (the barrier just consumed).
        // The sync below orders it before ALL our h(t) stores, which
        // transitively gate every h(t+1) arrival. Low skew: all warps just
        // left the same wait.
        if (t + 1 < TLEN && tid == 0)
            mbar_expect_tx(((t + 1) & 1) ? mb1 : mb0, HID * 4);
        __syncthreads();

        // prefetch pre for t+1 (hidden under the dot)
        float pv_next = 0.f;
        if (t + 1 < TLEN) {
            int tt1 = dir ? (TLEN - 2 - t) : (t + 1);
            pv_next = __ldg(&pre[tt1 * 1024 + gr]);
        }

        int q  = t & 1;        // buffer receiving h(t)
        int qp = q ^ 1;        // buffer holding h(t-1)

        // packed f32x2 dot: 64 FFMA2 over this thread's 128-wide K half
        const ulonglong2* h2 = (const ulonglong2*)&hbuf[qp][half * 128];
        unsigned long long a0 = 0ull, a1 = 0ull, a2 = 0ull, a3 = 0ull;
        #pragma unroll
        for (int i = 0; i < 32; i += 2) {
            ulonglong2 hv = h2[i];
            ulonglong2 hw = h2[i + 1];
            asm("fma.rn.f32x2 %0, %1, %2, %0;" : "+l"(a0) : "l"(w2[i].x),     "l"(hv.x));
            asm("fma.rn.f32x2 %0, %1, %2, %0;" : "+l"(a1) : "l"(w2[i].y),     "l"(hv.y));
            asm("fma.rn.f32x2 %0, %1, %2, %0;" : "+l"(a2) : "l"(w2[i + 1].x), "l"(hw.x));
            asm("fma.rn.f32x2 %0, %1, %2, %0;" : "+l"(a3) : "l"(w2[i + 1].y), "l"(hw.y));
        }
        float s0 = __uint_as_float((unsigned)(a0 & 0xffffffffull))
                 + __uint_as_float((unsigned)(a0 >> 32));
        float s1 = __uint_as_float((unsigned)(a1 & 0xffffffffull))
                 + __uint_as_float((unsigned)(a1 >> 32));
        float s2 = __uint_as_float((unsigned)(a2 & 0xffffffffull))
                 + __uint_as_float((unsigned)(a2 >> 32));
        float s3 = __uint_as_float((unsigned)(a3 & 0xffffffffull))
                 + __uint_as_float((unsigned)(a3 >> 32));
        float dot = (s0 + s1) + (s2 + s3);
        dot += __shfl_xor_sync(0xffffffffu, dot, 1);   // combine K halves
        dot += pv;                                     // + input projection

        // gather the 4 gates of this unit into all 8 group lanes
        float gi = __shfl_sync(0xffffffffu, dot, 0, 8);
        float gf = __shfl_sync(0xffffffffu, dot, 2, 8);
        float gg = __shfl_sync(0xffffffffu, dot, 4, 8);
        float go = __shfl_sync(0xffffffffu, dot, 6, 8);

        // redundant (deterministic) activation in all 8 lanes
        c = sigmoidf_(gf) * c + sigmoidf_(gi) * tanhf_(gg);
        float h = sigmoidf_(go) * tanhf_(c);

        int tt = dir ? (TLEN - 1 - t) : t;
        if (k == 0) out[(size_t)tt * ostride + off + u] = h;

        if (t + 1 < TLEN) {
            // push h to rank k's hbuf[q] + signal its mbar[q] (register-direct)
            st_async_f32(q ? r_h1 : r_h0, h, q ? r_mb1 : r_mb0);
        }
        pv = pv_next;
    }
    // no remote traffic after the final wait -> safe to exit without sync
}

// ------------------------------ heads --------------------------------------
__global__ __launch_bounds__(256) void heads_kernel(
    const float* __restrict__ x2, const float* __restrict__ Wm,
    float* __restrict__ sh, float* __restrict__ sd)
{
    int warp = threadIdx.x >> 5, lane = threadIdx.x & 31;
    int row = blockIdx.x * 8 + warp;
    const float4* xr = (const float4*)(x2 + (size_t)row * 512);
    const float4* wh = (const float4*)(Wm);
    const float4* wd = (const float4*)(Wm + 512);
    float a = 0.f, b = 0.f;
    #pragma unroll 4
    for (int i = lane; i < 128; i += 32) {
        float4 xv = xr[i]; float4 hv = wh[i]; float4 dv = wd[i];
        a += xv.x * hv.x + xv.y * hv.y + xv.z * hv.z + xv.w * hv.w;
        b += xv.x * dv.x + xv.y * dv.y + xv.z * dv.z + xv.w * dv.w;
    }
    #pragma unroll
    for (int o = 16; o; o >>= 1) {
        a += __shfl_xor_sync(0xffffffffu, a, o);
        b += __shfl_xor_sync(0xffffffffu, b, o);
    }
    if (lane == 0) { sh[row] = a; sd[row] = b; }
}

// ------------------------------ scores -------------------------------------
__global__ __launch_bounds__(256) void scores_kernel(
    const float* __restrict__ sh, const float* __restrict__ sd,
    const float* __restrict__ bm, float* __restrict__ out)
{
    float bb = __ldg(bm);
    size_t nquad = (size_t)TLEN * TLEN / 4;
    size_t stride = (size_t)gridDim.x * blockDim.x;
    for (size_t idx = (size_t)blockIdx.x * blockDim.x + threadIdx.x;
         idx < nquad; idx += stride) {
        int i  = (int)(idx >> 9);           // row (2048/4 = 512 quads per row)
        int j0 = (int)((idx & 511) << 2);   // first col of quad
        float si = sh[i];
        float4 r;
        r.x = (j0 + 0 > i) ? tanhf(si + sd[j0 + 0] + bb) : 0.f;
        r.y = (j0 + 1 > i) ? tanhf(si + sd[j0 + 1] + bb) : 0.f;
        r.z = (j0 + 2 > i) ? tanhf(si + sd[j0 + 2] + bb) : 0.f;
        r.w = (j0 + 3 > i) ? tanhf(si + sd[j0 + 3] + bb) : 0.f;
        *(float4*)(out + ((size_t)i * TLEN + j0)) = r;
    }
}

// ------------------------------ launch -------------------------------------
extern "C" void kernel_launch(void* const* d_in, const int* in_sizes, int n_in,
                              void* d_out, int out_size)
{
    const int*   word_idx = (const int*)  d_in[0];
    const float* E        = (const float*)d_in[1];
    const float* Wih0f    = (const float*)d_in[2];
    const float* Whh0f    = (const float*)d_in[3];
    const float* b0f      = (const float*)d_in[4];
    const float* Wih0b    = (const float*)d_in[5];
    const float* Whh0b    = (const float*)d_in[6];
    const float* b0b      = (const float*)d_in[7];
    const float* Wih1f    = (const float*)d_in[8];
    const float* Whh1f    = (const float*)d_in[9];
    const float* b1f      = (const float*)d_in[10];
    const float* Wih1b    = (const float*)d_in[11];
    const float* Whh1b    = (const float*)d_in[12];
    const float* b1b      = (const float*)d_in[13];
    const float* Wm       = (const float*)d_in[14];
    const float* bm       = (const float*)d_in[15];
    float* out = (float*)d_out;

    float *pre0f, *pre0b, *pre1f, *pre1b, *x1, *x2, *sh, *sd;
    cudaGetSymbolAddress((void**)&pre0f, g_pre0f);
    cudaGetSymbolAddress((void**)&pre0b, g_pre0b);
    cudaGetSymbolAddress((void**)&pre1f, g_pre1f);
    cudaGetSymbolAddress((void**)&pre1b, g_pre1b);
    cudaGetSymbolAddress((void**)&x1,    g_x1);
    cudaGetSymbolAddress((void**)&x2,    g_x2);
    cudaGetSymbolAddress((void**)&sh,    g_sh);
    cudaGetSymbolAddress((void**)&sd,    g_sd);

    dim3 gg(1024 / BN, TLEN / BM, 2);

    // layer 0 input projection (both directions, fused embedding gather)
    gemm_bias2_kernel<<<gg, 256>>>(nullptr, word_idx, E,
                                   Wih0f, b0f, pre0f, Wih0b, b0b, pre0b,
                                   TLEN, 1024, 256);
    // layer 0 recurrence (fwd + bwd clusters)
    lstm_layer_kernel<<<2 * CSZ, 256>>>(pre0f, pre0b, Whh0f, Whh0b, x1, 512);

    // layer 1 input projection
    gemm_bias2_kernel<<<gg, 256>>>(x1, nullptr, nullptr,
                                   Wih1f, b1f, pre1f, Wih1b, b1b, pre1b,
                                   TLEN, 1024, 512);
    // layer 1 recurrence
    lstm_layer_kernel<<<2 * CSZ, 256>>>(pre1f, pre1b, Whh1f, Whh1b, x2, 512);

    // scoring head
    heads_kernel<<<TLEN / 8, 256>>>(x2, Wm, sh, sd);
    scores_kernel<<<2048, 256>>>(sh, sd, bm, out);
}

// round 11
// speedup vs baseline: 1.9448x; 1.0047x over previous
#include <cuda_runtime.h>
#include <cuda_bf16.h>
#include <cstdint>
#include <cstddef>

// ---------------------------------------------------------------------------
// DependencyParsingNetwork: embed -> 2-layer biLSTM (T=2048, H=256) -> masked
// tanh score matrix [T,T].
//
//   1. gemm_bias2: pre0{f,b} = gather(E,idx) @ Wih0{f,b}^T + b    (one launch)
//   2. lstm_layer: cluster of 8 CTAs per direction; dot via packed
//      fma.rn.f32x2 (FFMA2); h exchanged via register-direct st.async +
//      mbarrier complete_tx; NO per-step __syncthreads (ordering closed by
//      data dependencies + a tid0 fence.proxy.async); activations split
//      across lanes via the sigmoid/tanh identity (single tanh path).
//   3. gemm_bias2: pre1{f,b} = x1 @ Wih1{f,b}^T + b
//   4. lstm_layer -> x2
//   5. heads + masked tanh scores
// ---------------------------------------------------------------------------

#define TLEN 2048
#define HID  256
#define CSZ  8      // cluster size (CTAs per direction)

// ------------------------- device scratch (static) -------------------------
__device__ float g_pre0f[TLEN * 1024];
__device__ float g_pre0b[TLEN * 1024];
__device__ float g_pre1f[TLEN * 1024];
__device__ float g_pre1b[TLEN * 1024];
__device__ float g_x1[TLEN * 512];
__device__ float g_x2[TLEN * 512];
__device__ float g_sh[TLEN];
__device__ float g_sd[TLEN];

// ------------------------------ helpers ------------------------------------
__device__ __forceinline__ uint32_t smem_u32(const void* p) {
    uint32_t a;
    asm("{ .reg .u64 t; cvta.to.shared.u64 t, %1; cvt.u32.u64 %0, t; }"
        : "=r"(a) : "l"(p));
    return a;
}

#define CLUSTER_SYNC() do { \
    asm volatile("barrier.cluster.arrive.aligned;" ::: "memory"); \
    asm volatile("barrier.cluster.wait.aligned;" ::: "memory"); \
} while (0)

__device__ __forceinline__ void mbar_init(uint32_t mbar, uint32_t count) {
    asm volatile("mbarrier.init.shared.b64 [%0], %1;" :: "r"(mbar), "r"(count)
                 : "memory");
}
__device__ __forceinline__ void mbar_expect_tx(uint32_t mbar, uint32_t bytes) {
    asm volatile("mbarrier.arrive.expect_tx.shared.b64 _, [%0], %1;"
                 :: "r"(mbar), "r"(bytes) : "memory");
}
// acquire at cluster scope: data was produced by remote-CTA st.async
__device__ __forceinline__ void mbar_wait_cluster(uint32_t mbar, uint32_t parity) {
    uint32_t done;
    asm volatile(
        "{\n\t.reg .pred p;\n\t"
        "mbarrier.try_wait.parity.acquire.cluster.shared::cta.b64 p, [%1], %2;\n\t"
        "selp.b32 %0, 1, 0, p;\n\t}"
        : "=r"(done) : "r"(mbar), "r"(parity) : "memory");
    while (!done) {
        asm volatile(
            "{\n\t.reg .pred p;\n\t"
            "mbarrier.try_wait.parity.acquire.cluster.shared::cta.b64 p, [%1], %2, 0x989680;\n\t"
            "selp.b32 %0, 1, 0, p;\n\t}"
            : "=r"(done) : "r"(mbar), "r"(parity) : "memory");
    }
}
__device__ __forceinline__ uint32_t mapa_u32(uint32_t laddr, uint32_t rank) {
    uint32_t r;
    asm volatile("mapa.shared::cluster.u32 %0, %1, %2;"
                 : "=r"(r) : "r"(laddr), "r"(rank));
    return r;
}
// remote smem store with tx-count completion on remote mbarrier
__device__ __forceinline__ void st_async_f32(uint32_t raddr, float v, uint32_t rbar) {
    asm volatile(
        "st.async.shared::cluster.mbarrier::complete_tx::bytes.b32 [%0], %1, [%2];"
        :: "r"(raddr), "r"(__float_as_uint(v)), "r"(rbar) : "memory");
}

__device__ __forceinline__ float tanhf_(float x) {
    float e = __expf(-2.f * fabsf(x));
    float t = __fdividef(1.f - e, 1.f + e);
    return x >= 0.f ? t : -t;
}

// ------------------------------ GEMM ---------------------------------------
// out{0,1}[M,N] = A[M,K] @ W{0,1}[N,K]^T + bias{0,1}[N]; z selects direction.
#define BM 64
#define BN 64
#define BK 16

__global__ __launch_bounds__(256) void gemm_bias2_kernel(
    const float* __restrict__ X, const int* __restrict__ idx,
    const float* __restrict__ E,
    const float* __restrict__ W0, const float* __restrict__ bias0,
    float* __restrict__ out0,
    const float* __restrict__ W1, const float* __restrict__ bias1,
    float* __restrict__ out1,
    int M, int N, int K)
{
    __shared__ __align__(16) float As[BK][BM + 4];
    __shared__ __align__(16) float Bs[BK][BN + 4];

    const float* W    = blockIdx.z ? W1    : W0;
    const float* bias = blockIdx.z ? bias1 : bias0;
    float*       out  = blockIdx.z ? out1  : out0;

    int tid = threadIdx.x;
    int m0 = blockIdx.y * BM, n0 = blockIdx.x * BN;
    int lrow = tid >> 2;          // 0..63
    int lcol = (tid & 3) * 4;     // 0,4,8,12
    int tx = tid & 15, ty = tid >> 4;

    float acc[4][4] = {};

    const float* Arow;
    if (idx) Arow = E + (size_t)idx[m0 + lrow] * K;
    else     Arow = X + (size_t)(m0 + lrow) * K;
    const float* Brow = W + (size_t)(n0 + lrow) * K;

    for (int k0 = 0; k0 < K; k0 += BK) {
        float4 av = *(const float4*)(Arow + k0 + lcol);
        float4 bv = *(const float4*)(Brow + k0 + lcol);
        As[lcol + 0][lrow] = av.x; As[lcol + 1][lrow] = av.y;
        As[lcol + 2][lrow] = av.z; As[lcol + 3][lrow] = av.w;
        Bs[lcol + 0][lrow] = bv.x; Bs[lcol + 1][lrow] = bv.y;
        Bs[lcol + 2][lrow] = bv.z; Bs[lcol + 3][lrow] = bv.w;
        __syncthreads();

        #pragma unroll
        for (int kk = 0; kk < BK; kk++) {
            float4 a = *(const float4*)&As[kk][ty * 4];
            float4 b = *(const float4*)&Bs[kk][tx * 4];
            acc[0][0] += a.x * b.x; acc[0][1] += a.x * b.y;
            acc[0][2] += a.x * b.z; acc[0][3] += a.x * b.w;
            acc[1][0] += a.y * b.x; acc[1][1] += a.y * b.y;
            acc[1][2] += a.y * b.z; acc[1][3] += a.y * b.w;
            acc[2][0] += a.z * b.x; acc[2][1] += a.z * b.y;
            acc[2][2] += a.z * b.z; acc[2][3] += a.z * b.w;
            acc[3][0] += a.w * b.x; acc[3][1] += a.w * b.y;
            acc[3][2] += a.w * b.z; acc[3][3] += a.w * b.w;
        }
        __syncthreads();
    }

    #pragma unroll
    for (int i = 0; i < 4; i++) {
        int m = m0 + ty * 4 + i;
        #pragma unroll
        for (int jj = 0; jj < 4; jj++) {
            int n = n0 + tx * 4 + jj;
            out[(size_t)m * N + n] = acc[i][jj] + bias[n];
        }
    }
}

// --------------------------- LSTM recurrence --------------------------------
// Thread map: tid = unit_local*8 + gate*2 + half  (32 units, 4 gates, 2 halves).
// Each 8-lane group owns one hidden unit. Dot = 64 packed fma.rn.f32x2 per
// thread (FFMA2). Per-gate activation applied IN the owning lane pair (one
// unified tanh path via sigmoid(x) = 0.5 + 0.5*tanh(x/2)), then gathered.
// No per-step __syncthreads:
//  - expect(t+1) ordering: tid0 posts expect, then fence.proxy.async, then its
//    own h(t) st.async; every h(t+1) arrival transitively requires that store.
//  - hbuf WAR: every pushed h depends via the shuffles on its group's reads of
//    the ENTIRE hbuf[qp], and h(t+1) needs all 32 of our units' h(t), so all
//    reads complete before any overwrite can arrive.
__global__ void __cluster_dims__(CSZ, 1, 1) __launch_bounds__(256, 1)
lstm_layer_kernel(const float* __restrict__ pre_f, const float* __restrict__ pre_b,
                  const float* __restrict__ Whh_f, const float* __restrict__ Whh_b,
                  float* __restrict__ out, int ostride)
{
    __shared__ __align__(16) float hbuf[2][HID];
    __shared__ __align__(8)  uint64_t mbar_store[2];

    int tid  = threadIdx.x;
    int rank = blockIdx.x & (CSZ - 1);
    int dir  = blockIdx.x / CSZ;

    const float* pre = dir ? pre_b : pre_f;
    const float* Whh = dir ? Whh_b : Whh_f;
    int off = dir ? HID : 0;

    int unit = tid >> 3;                 // 0..31 local unit
    int k    = tid & 7;                  // lane within unit group
    int gate = k >> 1;                   // 0..3 (i,f,g,o)
    int half = k & 1;                    // K half
    int gr   = gate * HID + rank * 32 + unit;   // gate row (0..1023)
    int u    = rank * 32 + unit;                // global hidden unit

    uint32_t mb0 = smem_u32(&mbar_store[0]);
    uint32_t mb1 = smem_u32(&mbar_store[1]);
    uint32_t hb  = smem_u32(&hbuf[0][0]);

    // load this thread's 128 Whh weights as 32 x (2 packed f32x2)
    ulonglong2 w2[32];
    const ulonglong2* wsrc =
        (const ulonglong2*)(Whh + (size_t)gr * HID + half * 128);
    #pragma unroll
    for (int i = 0; i < 32; i++) w2[i] = wsrc[i];

    // remote addresses for my h pushes (to rank k), per parity
    uint32_t r_h0  = mapa_u32(hb + (uint32_t)u * 4u, (uint32_t)k);
    uint32_t r_h1  = r_h0 + (uint32_t)HID * 4u;
    uint32_t r_mb0 = mapa_u32(mb0, (uint32_t)k);
    uint32_t r_mb1 = r_mb0 + 8u;

    // init: zero BOTH parity buffers (t=0 reads hbuf[1] as h(-1))
    hbuf[0][tid] = 0.f;
    hbuf[1][tid] = 0.f;
    if (tid < 2) mbar_init(tid ? mb1 : mb0, 1);
    __syncthreads();
    if (tid == 0) mbar_expect_tx(mb0, HID * 4);   // expect h(0): 1024B
    CLUSTER_SYNC();                      // inits + expect visible cluster-wide

    float c = 0.f;
    bool is_g = (gate == 2);
    int tt0 = dir ? (TLEN - 1) : 0;
    float pv = __ldg(&pre[tt0 * 1024 + gr]);      // prefetch for t = 0

    for (int t = 0; t < TLEN; t++) {
        // prefetch pre for t+1 BEFORE the wait (max slack, off critical path)
        float pv_next = 0.f;
        if (t + 1 < TLEN) {
            int tt1 = dir ? (TLEN - 2 - t) : (t + 1);
            pv_next = __ldg(&pre[tt1 * 1024 + gr]);
        }

        if (t > 0) {
            int tm = t - 1;   // wait h(t-1): mbar[tm&1], parity (tm>>1)&1
            mbar_wait_cluster(tm & 1 ? mb1 : mb0, (uint32_t)((tm >> 1) & 1));
        }
        // re-arm expect for h(t+1); the fence orders it (generic proxy) before
        // this thread's st.async (async proxy), which transitively gates every
        // h(t+1) arrival cluster-wide.
        if (t + 1 < TLEN && tid == 0) {
            mbar_expect_tx(((t + 1) & 1) ? mb1 : mb0, HID * 4);
            asm volatile("fence.proxy.async.shared::cta;" ::: "memory");
        }

        int q  = t & 1;        // buffer receiving h(t)
        int qp = q ^ 1;        // buffer holding h(t-1)

        // packed f32x2 dot: 64 FFMA2 over this thread's 128-wide K half
        const ulonglong2* h2 = (const ulonglong2*)&hbuf[qp][half * 128];
        unsigned long long a0 = 0ull, a1 = 0ull, a2 = 0ull, a3 = 0ull;
        #pragma unroll
        for (int i = 0; i < 32; i += 2) {
            ulonglong2 hv = h2[i];
            ulonglong2 hw = h2[i + 1];
            asm("fma.rn.f32x2 %0, %1, %2, %0;" : "+l"(a0) : "l"(w2[i].x),     "l"(hv.x));
            asm("fma.rn.f32x2 %0, %1, %2, %0;" : "+l"(a1) : "l"(w2[i].y),     "l"(hv.y));
            asm("fma.rn.f32x2 %0, %1, %2, %0;" : "+l"(a2) : "l"(w2[i + 1].x), "l"(hw.x));
            asm("fma.rn.f32x2 %0, %1, %2, %0;" : "+l"(a3) : "l"(w2[i + 1].y), "l"(hw.y));
        }
        float s0 = __uint_as_float((unsigned)(a0 & 0xffffffffull))
                 + __uint_as_float((unsigned)(a0 >> 32));
        float s1 = __uint_as_float((unsigned)(a1 & 0xffffffffull))
                 + __uint_as_float((unsigned)(a1 >> 32));
        float s2 = __uint_as_float((unsigned)(a2 & 0xffffffffull))
                 + __uint_as_float((unsigned)(a2 >> 32));
        float s3 = __uint_as_float((unsigned)(a3 & 0xffffffffull))
                 + __uint_as_float((unsigned)(a3 >> 32));
        float dot = (s0 + s1) + (s2 + s3);
        dot += __shfl_xor_sync(0xffffffffu, dot, 1);   // combine K halves
        dot += pv;                                     // + input projection

        // per-gate activation in the owning lane pair, single tanh path:
        //   gates i,f,o: sigmoid(x) = 0.5 + 0.5*tanh(x/2);  gate g: tanh(x)
        float z   = is_g ? dot : 0.5f * dot;
        float tz  = tanhf_(z);
        float act = is_g ? tz : fmaf(0.5f, tz, 0.5f);

        // gather the 4 activated gates into all 8 group lanes
        float ai = __shfl_sync(0xffffffffu, act, 0, 8);
        float af = __shfl_sync(0xffffffffu, act, 2, 8);
        float ag = __shfl_sync(0xffffffffu, act, 4, 8);
        float ao = __shfl_sync(0xffffffffu, act, 6, 8);

        // redundant (deterministic) cell update in all 8 lanes
        c = af * c + ai * ag;
        float h = ao * tanhf_(c);

        int tt = dir ? (TLEN - 1 - t) : t;
        if (k == 0) out[(size_t)tt * ostride + off + u] = h;

        if (t + 1 < TLEN) {
            // push h to rank k's hbuf[q] + signal its mbar[q] (register-direct)
            st_async_f32(q ? r_h1 : r_h0, h, q ? r_mb1 : r_mb0);
        }
        pv = pv_next;
    }
    // no remote traffic after the final wait -> safe to exit without sync
}

// ------------------------------ heads --------------------------------------
__global__ __launch_bounds__(256) void heads_kernel(
    const float* __restrict__ x2, const float* __restrict__ Wm,
    float* __restrict__ sh, float* __restrict__ sd)
{
    int warp = threadIdx.x >> 5, lane = threadIdx.x & 31;
    int row = blockIdx.x * 8 + warp;
    const float4* xr = (const float4*)(x2 + (size_t)row * 512);
    const float4* wh = (const float4*)(Wm);
    const float4* wd = (const float4*)(Wm + 512);
    float a = 0.f, b = 0.f;
    #pragma unroll 4
    for (int i = lane; i < 128; i += 32) {
        float4 xv = xr[i]; float4 hv = wh[i]; float4 dv = wd[i];
        a += xv.x * hv.x + xv.y * hv.y + xv.z * hv.z + xv.w * hv.w;
        b += xv.x * dv.x + xv.y * dv.y + xv.z * dv.z + xv.w * dv.w;
    }
    #pragma unroll
    for (int o = 16; o; o >>= 1) {
        a += __shfl_xor_sync(0xffffffffu, a, o);
        b += __shfl_xor_sync(0xffffffffu, b, o);
    }
    if (lane == 0) { sh[row] = a; sd[row] = b; }
}

// ------------------------------ scores -------------------------------------
__global__ __launch_bounds__(256) void scores_kernel(
    const float* __restrict__ sh, const float* __restrict__ sd,
    const float* __restrict__ bm, float* __restrict__ out)
{
    float bb = __ldg(bm);
    size_t nquad = (size_t)TLEN * TLEN / 4;
    size_t stride = (size_t)gridDim.x * blockDim.x;
    for (size_t idx = (size_t)blockIdx.x * blockDim.x + threadIdx.x;
         idx < nquad; idx += stride) {
        int i  = (int)(idx >> 9);           // row (2048/4 = 512 quads per row)
        int j0 = (int)((idx & 511) << 2);   // first col of quad
        float si = sh[i];
        float4 r;
        r.x = (j0 + 0 > i) ? tanhf(si + sd[j0 + 0] + bb) : 0.f;
        r.y = (j0 + 1 > i) ? tanhf(si + sd[j0 + 1] + bb) : 0.f;
        r.z = (j0 + 2 > i) ? tanhf(si + sd[j0 + 2] + bb) : 0.f;
        r.w = (j0 + 3 > i) ? tanhf(si + sd[j0 + 3] + bb) : 0.f;
        *(float4*)(out + ((size_t)i * TLEN + j0)) = r;
    }
}

// ------------------------------ launch -------------------------------------
extern "C" void kernel_launch(void* const* d_in, const int* in_sizes, int n_in,
                              void* d_out, int out_size)
{
    const int*   word_idx = (const int*)  d_in[0];
    const float* E        = (const float*)d_in[1];
    const float* Wih0f    = (const float*)d_in[2];
    const float* Whh0f    = (const float*)d_in[3];
    const float* b0f      = (const float*)d_in[4];
    const float* Wih0b    = (const float*)d_in[5];
    const float* Whh0b    = (const float*)d_in[6];
    const float* b0b      = (const float*)d_in[7];
    const float* Wih1f    = (const float*)d_in[8];
    const float* Whh1f    = (const float*)d_in[9];
    const float* b1f      = (const float*)d_in[10];
    const float* Wih1b    = (const float*)d_in[11];
    const float* Whh1b    = (const float*)d_in[12];
    const float* b1b      = (const float*)d_in[13];
    const float* Wm       = (const float*)d_in[14];
    const float* bm       = (const float*)d_in[15];
    float* out = (float*)d_out;

    float *pre0f, *pre0b, *pre1f, *pre1b, *x1, *x2, *sh, *sd;
    cudaGetSymbolAddress((void**)&pre0f, g_pre0f);
    cudaGetSymbolAddress((void**)&pre0b, g_pre0b);
    cudaGetSymbolAddress((void**)&pre1f, g_pre1f);
    cudaGetSymbolAddress((void**)&pre1b, g_pre1b);
    cudaGetSymbolAddress((void**)&x1,    g_x1);
    cudaGetSymbolAddress((void**)&x2,    g_x2);
    cudaGetSymbolAddress((void**)&sh,    g_sh);
    cudaGetSymbolAddress((void**)&sd,    g_sd);

    dim3 gg(1024 / BN, TLEN / BM, 2);

    // layer 0 input projection (both directions, fused embedding gather)
    gemm_bias2_kernel<<<gg, 256>>>(nullptr, word_idx, E,
                                   Wih0f, b0f, pre0f, Wih0b, b0b, pre0b,
                                   TLEN, 1024, 256);
    // layer 0 recurrence (fwd + bwd clusters)
    lstm_layer_kernel<<<2 * CSZ, 256>>>(pre0f, pre0b, Whh0f, Whh0b, x1, 512);

    // layer 1 input projection
    gemm_bias2_kernel<<<gg, 256>>>(x1, nullptr, nullptr,
                                   Wih1f, b1f, pre1f, Wih1b, b1b, pre1b,
                                   TLEN, 1024, 512);
    // layer 1 recurrence
    lstm_layer_kernel<<<2 * CSZ, 256>>>(pre1f, pre1b, Whh1f, Whh1b, x2, 512);

    // scoring head
    heads_kernel<<<TLEN / 8, 256>>>(x2, Wm, sh, sd);
    scores_kernel<<<2048, 256>>>(sh, sd, bm, out);
}

// round 12
// speedup vs baseline: 2.2394x; 1.1515x over previous
#include <cuda_runtime.h>
#include <cuda_bf16.h>
#include <cstdint>
#include <cstddef>

// ---------------------------------------------------------------------------
// DependencyParsingNetwork: embed -> 2-layer biLSTM (T=2048, H=256) -> masked
// tanh score matrix [T,T].
//
//   1. gemm_bias2: pre0{f,b} = gather(E,idx) @ Wih0{f,b}^T + b    (one launch)
//   2. lstm_layer: cluster of 8 CTAs per direction. Thread (unit,k) owns
//      K-chunk k for all 4 gates: 8 LDS.128/step (rotated, bank-conflict-
//      free), 64 FFMA2, width-8 butterfly reduce, lane-split activations.
//      h exchanged via register-direct st.async + mbarrier complete_tx;
//      no per-step __syncthreads.
//   3. gemm_bias2: pre1{f,b} = x1 @ Wih1{f,b}^T + b
//   4. lstm_layer -> x2
//   5. heads + masked tanh scores
// ---------------------------------------------------------------------------

#define TLEN 2048
#define HID  256
#define CSZ  8      // cluster size (CTAs per direction)

// ------------------------- device scratch (static) -------------------------
__device__ float g_pre0f[TLEN * 1024];
__device__ float g_pre0b[TLEN * 1024];
__device__ float g_pre1f[TLEN * 1024];
__device__ float g_pre1b[TLEN * 1024];
__device__ float g_x1[TLEN * 512];
__device__ float g_x2[TLEN * 512];
__device__ float g_sh[TLEN];
__device__ float g_sd[TLEN];

// ------------------------------ helpers ------------------------------------
__device__ __forceinline__ uint32_t smem_u32(const void* p) {
    uint32_t a;
    asm("{ .reg .u64 t; cvta.to.shared.u64 t, %1; cvt.u32.u64 %0, t; }"
        : "=r"(a) : "l"(p));
    return a;
}

#define CLUSTER_SYNC() do { \
    asm volatile("barrier.cluster.arrive.aligned;" ::: "memory"); \
    asm volatile("barrier.cluster.wait.aligned;" ::: "memory"); \
} while (0)

__device__ __forceinline__ void mbar_init(uint32_t mbar, uint32_t count) {
    asm volatile("mbarrier.init.shared.b64 [%0], %1;" :: "r"(mbar), "r"(count)
                 : "memory");
}
__device__ __forceinline__ void mbar_expect_tx(uint32_t mbar, uint32_t bytes) {
    asm volatile("mbarrier.arrive.expect_tx.shared.b64 _, [%0], %1;"
                 :: "r"(mbar), "r"(bytes) : "memory");
}
// acquire at cluster scope: data was produced by remote-CTA st.async
__device__ __forceinline__ void mbar_wait_cluster(uint32_t mbar, uint32_t parity) {
    uint32_t done;
    asm volatile(
        "{\n\t.reg .pred p;\n\t"
        "mbarrier.try_wait.parity.acquire.cluster.shared::cta.b64 p, [%1], %2;\n\t"
        "selp.b32 %0, 1, 0, p;\n\t}"
        : "=r"(done) : "r"(mbar), "r"(parity) : "memory");
    while (!done) {
        asm volatile(
            "{\n\t.reg .pred p;\n\t"
            "mbarrier.try_wait.parity.acquire.cluster.shared::cta.b64 p, [%1], %2, 0x989680;\n\t"
            "selp.b32 %0, 1, 0, p;\n\t}"
            : "=r"(done) : "r"(mbar), "r"(parity) : "memory");
    }
}
__device__ __forceinline__ uint32_t mapa_u32(uint32_t laddr, uint32_t rank) {
    uint32_t r;
    asm volatile("mapa.shared::cluster.u32 %0, %1, %2;"
                 : "=r"(r) : "r"(laddr), "r"(rank));
    return r;
}
// remote smem store with tx-count completion on remote mbarrier
__device__ __forceinline__ void st_async_f32(uint32_t raddr, float v, uint32_t rbar) {
    asm volatile(
        "st.async.shared::cluster.mbarrier::complete_tx::bytes.b32 [%0], %1, [%2];"
        :: "r"(raddr), "r"(__float_as_uint(v)), "r"(rbar) : "memory");
}

__device__ __forceinline__ float tanhf_(float x) {
    float e = __expf(-2.f * fabsf(x));
    float t = __fdividef(1.f - e, 1.f + e);
    return x >= 0.f ? t : -t;
}

// ------------------------------ GEMM ---------------------------------------
// out{0,1}[M,N] = A[M,K] @ W{0,1}[N,K]^T + bias{0,1}[N]; z selects direction.
#define BM 64
#define BN 64
#define BK 16

__global__ __launch_bounds__(256) void gemm_bias2_kernel(
    const float* __restrict__ X, const int* __restrict__ idx,
    const float* __restrict__ E,
    const float* __restrict__ W0, const float* __restrict__ bias0,
    float* __restrict__ out0,
    const float* __restrict__ W1, const float* __restrict__ bias1,
    float* __restrict__ out1,
    int M, int N, int K)
{
    __shared__ __align__(16) float As[BK][BM + 4];
    __shared__ __align__(16) float Bs[BK][BN + 4];

    const float* W    = blockIdx.z ? W1    : W0;
    const float* bias = blockIdx.z ? bias1 : bias0;
    float*       out  = blockIdx.z ? out1  : out0;

    int tid = threadIdx.x;
    int m0 = blockIdx.y * BM, n0 = blockIdx.x * BN;
    int lrow = tid >> 2;          // 0..63
    int lcol = (tid & 3) * 4;     // 0,4,8,12
    int tx = tid & 15, ty = tid >> 4;

    float acc[4][4] = {};

    const float* Arow;
    if (idx) Arow = E + (size_t)idx[m0 + lrow] * K;
    else     Arow = X + (size_t)(m0 + lrow) * K;
    const float* Brow = W + (size_t)(n0 + lrow) * K;

    for (int k0 = 0; k0 < K; k0 += BK) {
        float4 av = *(const float4*)(Arow + k0 + lcol);
        float4 bv = *(const float4*)(Brow + k0 + lcol);
        As[lcol + 0][lrow] = av.x; As[lcol + 1][lrow] = av.y;
        As[lcol + 2][lrow] = av.z; As[lcol + 3][lrow] = av.w;
        Bs[lcol + 0][lrow] = bv.x; Bs[lcol + 1][lrow] = bv.y;
        Bs[lcol + 2][lrow] = bv.z; Bs[lcol + 3][lrow] = bv.w;
        __syncthreads();

        #pragma unroll
        for (int kk = 0; kk < BK; kk++) {
            float4 a = *(const float4*)&As[kk][ty * 4];
            float4 b = *(const float4*)&Bs[kk][tx * 4];
            acc[0][0] += a.x * b.x; acc[0][1] += a.x * b.y;
            acc[0][2] += a.x * b.z; acc[0][3] += a.x * b.w;
            acc[1][0] += a.y * b.x; acc[1][1] += a.y * b.y;
            acc[1][2] += a.y * b.z; acc[1][3] += a.y * b.w;
            acc[2][0] += a.z * b.x; acc[2][1] += a.z * b.y;
            acc[2][2] += a.z * b.z; acc[2][3] += a.z * b.w;
            acc[3][0] += a.w * b.x; acc[3][1] += a.w * b.y;
            acc[3][2] += a.w * b.z; acc[3][3] += a.w * b.w;
        }
        __syncthreads();
    }

    #pragma unroll
    for (int i = 0; i < 4; i++) {
        int m = m0 + ty * 4 + i;
        #pragma unroll
        for (int jj = 0; jj < 4; jj++) {
            int n = n0 + tx * 4 + jj;
            out[(size_t)m * N + n] = acc[i][jj] + bias[n];
        }
    }
}

// --------------------------- LSTM recurrence --------------------------------
// Thread map: tid = unit_local*8 + k. Thread (unit,k) owns h K-chunk k
// (32 floats) for ALL 4 gates of its unit (4x32 = 128 weights in regs).
// Per step: 8 rotated LDS.128 (bank-conflict-free: lane k reads line
// (j+k)&7 of its chunk; weights pre-permuted to match), 64 FFMA2 into 4
// gate partials, width-8 butterfly reduce (all lanes get all 4 sums),
// lane-split activation (gate = k&3, unified tanh path), width-8 gather,
// redundant cell update, register-direct st.async exchange. No per-step
// __syncthreads: each group's lanes jointly read ALL of hbuf[qp] before
// producing h, so the R11 WAR/ordering proofs carry over.
__global__ void __cluster_dims__(CSZ, 1, 1) __launch_bounds__(256, 1)
lstm_layer_kernel(const float* __restrict__ pre_f, const float* __restrict__ pre_b,
                  const float* __restrict__ Whh_f, const float* __restrict__ Whh_b,
                  float* __restrict__ out, int ostride)
{
    __shared__ __align__(16) float hbuf[2][HID];
    __shared__ __align__(8)  uint64_t mbar_store[2];

    int tid  = threadIdx.x;
    int rank = blockIdx.x & (CSZ - 1);
    int dir  = blockIdx.x / CSZ;

    const float* pre = dir ? pre_b : pre_f;
    const float* Whh = dir ? Whh_b : Whh_f;
    int off = dir ? HID : 0;

    int unit = tid >> 3;                 // 0..31 local unit
    int k    = tid & 7;                  // lane within unit group = K chunk
    int u    = rank * 32 + unit;         // global hidden unit
    int myg  = k & 3;                    // gate this lane activates

    uint32_t mb0 = smem_u32(&mbar_store[0]);
    uint32_t mb1 = smem_u32(&mbar_store[1]);
    uint32_t hb  = smem_u32(&hbuf[0][0]);

    // Weights: w2[g][j] = 16B line of gate-g row at K offset k*32 + rot(j)*4,
    // rot(j) = (j+k)&7 — matches the rotated h line loaded at step j.
    ulonglong2 w2[4][8];
    #pragma unroll
    for (int g = 0; g < 4; g++) {
        const float* wrow = Whh + (size_t)(g * HID + u) * HID + k * 32;
        #pragma unroll
        for (int j = 0; j < 8; j++) {
            int rot = (j + k) & 7;
            w2[g][j] = *(const ulonglong2*)(wrow + rot * 4);
        }
    }

    // remote addresses for my h pushes (to rank k), per parity
    uint32_t r_h0  = mapa_u32(hb + (uint32_t)u * 4u, (uint32_t)k);
    uint32_t r_h1  = r_h0 + (uint32_t)HID * 4u;
    uint32_t r_mb0 = mapa_u32(mb0, (uint32_t)k);
    uint32_t r_mb1 = r_mb0 + 8u;

    // init: zero BOTH parity buffers (t=0 reads hbuf[1] as h(-1))
    hbuf[0][tid] = 0.f;
    hbuf[1][tid] = 0.f;
    if (tid < 2) mbar_init(tid ? mb1 : mb0, 1);
    __syncthreads();
    if (tid == 0) mbar_expect_tx(mb0, HID * 4);   // expect h(0): 1024B
    CLUSTER_SYNC();                      // inits + expect visible cluster-wide

    float c = 0.f;
    // pre row for gate k (lanes k<4 carry it; k>=4 contribute 0)
    int tt0 = dir ? (TLEN - 1) : 0;
    float pv = (k < 4) ? __ldg(&pre[tt0 * 1024 + k * HID + u]) : 0.f;

    for (int t = 0; t < TLEN; t++) {
        // prefetch pre for t+1 BEFORE the wait (max slack, off critical path)
        float pv_next = 0.f;
        if (t + 1 < TLEN && k < 4) {
            int tt1 = dir ? (TLEN - 2 - t) : (t + 1);
            pv_next = __ldg(&pre[tt1 * 1024 + k * HID + u]);
        }

        if (t > 0) {
            int tm = t - 1;   // wait h(t-1): mbar[tm&1], parity (tm>>1)&1
            mbar_wait_cluster(tm & 1 ? mb1 : mb0, (uint32_t)((tm >> 1) & 1));
        }
        // re-arm expect for h(t+1); the fence orders it (generic proxy) before
        // this thread's st.async (async proxy), which transitively gates every
        // h(t+1) arrival cluster-wide.
        if (t + 1 < TLEN && tid == 0) {
            mbar_expect_tx(((t + 1) & 1) ? mb1 : mb0, HID * 4);
            asm volatile("fence.proxy.async.shared::cta;" ::: "memory");
        }

        int q  = t & 1;        // buffer receiving h(t)
        int qp = q ^ 1;        // buffer holding h(t-1)

        // 8 rotated LDS.128 of my 32-float chunk; 4 gate partials via FFMA2
        const char* hbase = (const char*)&hbuf[qp][k * 32];
        unsigned long long a0[4] = {0ull, 0ull, 0ull, 0ull};
        unsigned long long a1[4] = {0ull, 0ull, 0ull, 0ull};
        #pragma unroll
        for (int j = 0; j < 8; j++) {
            int rot = (j + k) & 7;
            ulonglong2 hv = *(const ulonglong2*)(hbase + rot * 16);
            #pragma unroll
            for (int g = 0; g < 4; g++) {
                asm("fma.rn.f32x2 %0, %1, %2, %0;"
                    : "+l"(a0[g]) : "l"(w2[g][j].x), "l"(hv.x));
                asm("fma.rn.f32x2 %0, %1, %2, %0;"
                    : "+l"(a1[g]) : "l"(w2[g][j].y), "l"(hv.y));
            }
        }
        // collapse packed accumulators -> 4 scalar partials; fold pre in the
        // lane that owns that gate's pre value (k<4, gate k)
        float s[4];
        #pragma unroll
        for (int g = 0; g < 4; g++) {
            float lo0 = __uint_as_float((unsigned)(a0[g] & 0xffffffffull));
            float hi0 = __uint_as_float((unsigned)(a0[g] >> 32));
            float lo1 = __uint_as_float((unsigned)(a1[g] & 0xffffffffull));
            float hi1 = __uint_as_float((unsigned)(a1[g] >> 32));
            s[g] = (lo0 + hi0) + (lo1 + hi1);
            s[g] += (k == g) ? pv : 0.f;
        }
        // width-8 butterfly: all lanes end with full sums of all 4 gates
        #pragma unroll
        for (int m = 1; m < 8; m <<= 1) {
            #pragma unroll
            for (int g = 0; g < 4; g++)
                s[g] += __shfl_xor_sync(0xffffffffu, s[g], m, 8);
        }

        // lane-split activation, single tanh path:
        //   gates i,f,o: sigmoid(x) = 0.5 + 0.5*tanh(x/2);  gate g(=2): tanh
        float x   = (myg == 0) ? s[0] : (myg == 1) ? s[1]
                  : (myg == 2) ? s[2] : s[3];
        float z   = (myg == 2) ? x : 0.5f * x;
        float tz  = tanhf_(z);
        float act = (myg == 2) ? tz : fmaf(0.5f, tz, 0.5f);

        // gather the 4 activated gates (from lanes 0..3 of the group)
        float ai = __shfl_sync(0xffffffffu, act, 0, 8);
        float af = __shfl_sync(0xffffffffu, act, 1, 8);
        float ag = __shfl_sync(0xffffffffu, act, 2, 8);
        float ao = __shfl_sync(0xffffffffu, act, 3, 8);

        // redundant (deterministic) cell update in all 8 lanes
        c = af * c + ai * ag;
        float h = ao * tanhf_(c);

        int tt = dir ? (TLEN - 1 - t) : t;
        if (k == 0) out[(size_t)tt * ostride + off + u] = h;

        if (t + 1 < TLEN) {
            // push h to rank k's hbuf[q] + signal its mbar[q] (register-direct)
            st_async_f32(q ? r_h1 : r_h0, h, q ? r_mb1 : r_mb0);
        }
        pv = pv_next;
    }
    // no remote traffic after the final wait -> safe to exit without sync
}

// ------------------------------ heads --------------------------------------
__global__ __launch_bounds__(256) void heads_kernel(
    const float* __restrict__ x2, const float* __restrict__ Wm,
    float* __restrict__ sh, float* __restrict__ sd)
{
    int warp = threadIdx.x >> 5, lane = threadIdx.x & 31;
    int row = blockIdx.x * 8 + warp;
    const float4* xr = (const float4*)(x2 + (size_t)row * 512);
    const float4* wh = (const float4*)(Wm);
    const float4* wd = (const float4*)(Wm + 512);
    float a = 0.f, b = 0.f;
    #pragma unroll 4
    for (int i = lane; i < 128; i += 32) {
        float4 xv = xr[i]; float4 hv = wh[i]; float4 dv = wd[i];
        a += xv.x * hv.x + xv.y * hv.y + xv.z * hv.z + xv.w * hv.w;
        b += xv.x * dv.x + xv.y * dv.y + xv.z * dv.z + xv.w * dv.w;
    }
    #pragma unroll
    for (int o = 16; o; o >>= 1) {
        a += __shfl_xor_sync(0xffffffffu, a, o);
        b += __shfl_xor_sync(0xffffffffu, b, o);
    }
    if (lane == 0) { sh[row] = a; sd[row] = b; }
}

// ------------------------------ scores -------------------------------------
__global__ __launch_bounds__(256) void scores_kernel(
    const float* __restrict__ sh, const float* __restrict__ sd,
    const float* __restrict__ bm, float* __restrict__ out)
{
    float bb = __ldg(bm);
    size_t nquad = (size_t)TLEN * TLEN / 4;
    size_t stride = (size_t)gridDim.x * blockDim.x;
    for (size_t idx = (size_t)blockIdx.x * blockDim.x + threadIdx.x;
         idx < nquad; idx += stride) {
        int i  = (int)(idx >> 9);           // row (2048/4 = 512 quads per row)
        int j0 = (int)((idx & 511) << 2);   // first col of quad
        float si = sh[i];
        float4 r;
        r.x = (j0 + 0 > i) ? tanhf(si + sd[j0 + 0] + bb) : 0.f;
        r.y = (j0 + 1 > i) ? tanhf(si + sd[j0 + 1] + bb) : 0.f;
        r.z = (j0 + 2 > i) ? tanhf(si + sd[j0 + 2] + bb) : 0.f;
        r.w = (j0 + 3 > i) ? tanhf(si + sd[j0 + 3] + bb) : 0.f;
        *(float4*)(out + ((size_t)i * TLEN + j0)) = r;
    }
}

// ------------------------------ launch -------------------------------------
extern "C" void kernel_launch(void* const* d_in, const int* in_sizes, int n_in,
                              void* d_out, int out_size)
{
    const int*   word_idx = (const int*)  d_in[0];
    const float* E        = (const float*)d_in[1];
    const float* Wih0f    = (const float*)d_in[2];
    const float* Whh0f    = (const float*)d_in[3];
    const float* b0f      = (const float*)d_in[4];
    const float* Wih0b    = (const float*)d_in[5];
    const float* Whh0b    = (const float*)d_in[6];
    const float* b0b      = (const float*)d_in[7];
    const float* Wih1f    = (const float*)d_in[8];
    const float* Whh1f    = (const float*)d_in[9];
    const float* b1f      = (const float*)d_in[10];
    const float* Wih1b    = (const float*)d_in[11];
    const float* Whh1b    = (const float*)d_in[12];
    const float* b1b      = (const float*)d_in[13];
    const float* Wm       = (const float*)d_in[14];
    const float* bm       = (const float*)d_in[15];
    float* out = (float*)d_out;

    float *pre0f, *pre0b, *pre1f, *pre1b, *x1, *x2, *sh, *sd;
    cudaGetSymbolAddress((void**)&pre0f, g_pre0f);
    cudaGetSymbolAddress((void**)&pre0b, g_pre0b);
    cudaGetSymbolAddress((void**)&pre1f, g_pre1f);
    cudaGetSymbolAddress((void**)&pre1b, g_pre1b);
    cudaGetSymbolAddress((void**)&x1,    g_x1);
    cudaGetSymbolAddress((void**)&x2,    g_x2);
    cudaGetSymbolAddress((void**)&sh,    g_sh);
    cudaGetSymbolAddress((void**)&sd,    g_sd);

    dim3 gg(1024 / BN, TLEN / BM, 2);

    // layer 0 input projection (both directions, fused embedding gather)
    gemm_bias2_kernel<<<gg, 256>>>(nullptr, word_idx, E,
                                   Wih0f, b0f, pre0f, Wih0b, b0b, pre0b,
                                   TLEN, 1024, 256);
    // layer 0 recurrence (fwd + bwd clusters)
    lstm_layer_kernel<<<2 * CSZ, 256>>>(pre0f, pre0b, Whh0f, Whh0b, x1, 512);

    // layer 1 input projection
    gemm_bias2_kernel<<<gg, 256>>>(x1, nullptr, nullptr,
                                   Wih1f, b1f, pre1f, Wih1b, b1b, pre1b,
                                   TLEN, 1024, 512);
    // layer 1 recurrence
    lstm_layer_kernel<<<2 * CSZ, 256>>>(pre1f, pre1b, Whh1f, Whh1b, x2, 512);

    // scoring head
    heads_kernel<<<TLEN / 8, 256>>>(x2, Wm, sh, sd);
    scores_kernel<<<2048, 256>>>(sh, sd, bm, out);
}

// round 14
// speedup vs baseline: 2.7948x; 1.2480x over previous
#include <cuda_runtime.h>
#include <cuda_bf16.h>
#include <cstdint>
#include <cstddef>

// ---------------------------------------------------------------------------
// DependencyParsingNetwork: embed -> 2-layer biLSTM (T=2048, H=256) -> masked
// tanh score matrix [T,T].
//
//   1. gemm_bias2: pre0{f,b} = gather(E,idx) @ Wih0{f,b}^T + b    (one launch)
//   2. lstm_layer: cluster of 8 CTAs per direction. Thread (unit,k) owns
//      K-chunk k for all 4 gates: 8 rotated bank-conflict-free LDS.128,
//      64 FFMA2, width-8 butterfly, lane-split MUFU tanh activations.
//      h exchanged via register-direct st.async + 4-deep mbarrier ring;
//      expect_tx posted 2 steps ahead (fence overlaps the wait stall);
//      no per-step __syncthreads.
//   3. gemm_bias2: pre1{f,b} = x1 @ Wih1{f,b}^T + b
//   4. lstm_layer -> x2
//   5. heads + masked tanh scores
// ---------------------------------------------------------------------------

#define TLEN 2048
#define HID  256
#define CSZ  8      // cluster size (CTAs per direction)

// ------------------------- device scratch (static) -------------------------
__device__ float g_pre0f[TLEN * 1024];
__device__ float g_pre0b[TLEN * 1024];
__device__ float g_pre1f[TLEN * 1024];
__device__ float g_pre1b[TLEN * 1024];
__device__ float g_x1[TLEN * 512];
__device__ float g_x2[TLEN * 512];
__device__ float g_sh[TLEN];
__device__ float g_sd[TLEN];

// ------------------------------ helpers ------------------------------------
__device__ __forceinline__ uint32_t smem_u32(const void* p) {
    uint32_t a;
    asm("{ .reg .u64 t; cvta.to.shared.u64 t, %1; cvt.u32.u64 %0, t; }"
        : "=r"(a) : "l"(p));
    return a;
}

#define CLUSTER_SYNC() do { \
    asm volatile("barrier.cluster.arrive.aligned;" ::: "memory"); \
    asm volatile("barrier.cluster.wait.aligned;" ::: "memory"); \
} while (0)

__device__ __forceinline__ void mbar_init(uint32_t mbar, uint32_t count) {
    asm volatile("mbarrier.init.shared.b64 [%0], %1;" :: "r"(mbar), "r"(count)
                 : "memory");
}
__device__ __forceinline__ void mbar_expect_tx(uint32_t mbar, uint32_t bytes) {
    asm volatile("mbarrier.arrive.expect_tx.shared.b64 _, [%0], %1;"
                 :: "r"(mbar), "r"(bytes) : "memory");
}
// acquire at cluster scope: data was produced by remote-CTA st.async
__device__ __forceinline__ void mbar_wait_cluster(uint32_t mbar, uint32_t parity) {
    uint32_t done;
    asm volatile(
        "{\n\t.reg .pred p;\n\t"
        "mbarrier.try_wait.parity.acquire.cluster.shared::cta.b64 p, [%1], %2;\n\t"
        "selp.b32 %0, 1, 0, p;\n\t}"
        : "=r"(done) : "r"(mbar), "r"(parity) : "memory");
    while (!done) {
        asm volatile(
            "{\n\t.reg .pred p;\n\t"
            "mbarrier.try_wait.parity.acquire.cluster.shared::cta.b64 p, [%1], %2, 0x989680;\n\t"
            "selp.b32 %0, 1, 0, p;\n\t}"
            : "=r"(done) : "r"(mbar), "r"(parity) : "memory");
    }
}
__device__ __forceinline__ uint32_t mapa_u32(uint32_t laddr, uint32_t rank) {
    uint32_t r;
    asm volatile("mapa.shared::cluster.u32 %0, %1, %2;"
                 : "=r"(r) : "r"(laddr), "r"(rank));
    return r;
}
// remote smem store with tx-count completion on remote mbarrier
__device__ __forceinline__ void st_async_f32(uint32_t raddr, float v, uint32_t rbar) {
    asm volatile(
        "st.async.shared::cluster.mbarrier::complete_tx::bytes.b32 [%0], %1, [%2];"
        :: "r"(raddr), "r"(__float_as_uint(v)), "r"(rbar) : "memory");
}

// MUFU tanh: single-instruction approx (rel err ~5e-4) — used only inside the
// recurrence where the contractive dynamics damp it; scores use exact tanhf.
__device__ __forceinline__ float tanh_mufu(float x) {
    float y;
    asm("tanh.approx.f32 %0, %1;" : "=f"(y) : "f"(x));
    return y;
}

// ------------------------------ GEMM ---------------------------------------
// out{0,1}[M,N] = A[M,K] @ W{0,1}[N,K]^T + bias{0,1}[N]; z selects direction.
#define BM 64
#define BN 64
#define BK 16

__global__ __launch_bounds__(256) void gemm_bias2_kernel(
    const float* __restrict__ X, const int* __restrict__ idx,
    const float* __restrict__ E,
    const float* __restrict__ W0, const float* __restrict__ bias0,
    float* __restrict__ out0,
    const float* __restrict__ W1, const float* __restrict__ bias1,
    float* __restrict__ out1,
    int M, int N, int K)
{
    __shared__ __align__(16) float As[BK][BM + 4];
    __shared__ __align__(16) float Bs[BK][BN + 4];

    const float* W    = blockIdx.z ? W1    : W0;
    const float* bias = blockIdx.z ? bias1 : bias0;
    float*       out  = blockIdx.z ? out1  : out0;

    int tid = threadIdx.x;
    int m0 = blockIdx.y * BM, n0 = blockIdx.x * BN;
    int lrow = tid >> 2;          // 0..63
    int lcol = (tid & 3) * 4;     // 0,4,8,12
    int tx = tid & 15, ty = tid >> 4;

    float acc[4][4] = {};

    const float* Arow;
    if (idx) Arow = E + (size_t)idx[m0 + lrow] * K;
    else     Arow = X + (size_t)(m0 + lrow) * K;
    const float* Brow = W + (size_t)(n0 + lrow) * K;

    for (int k0 = 0; k0 < K; k0 += BK) {
        float4 av = *(const float4*)(Arow + k0 + lcol);
        float4 bv = *(const float4*)(Brow + k0 + lcol);
        As[lcol + 0][lrow] = av.x; As[lcol + 1][lrow] = av.y;
        As[lcol + 2][lrow] = av.z; As[lcol + 3][lrow] = av.w;
        Bs[lcol + 0][lrow] = bv.x; Bs[lcol + 1][lrow] = bv.y;
        Bs[lcol + 2][lrow] = bv.z; Bs[lcol + 3][lrow] = bv.w;
        __syncthreads();

        #pragma unroll
        for (int kk = 0; kk < BK; kk++) {
            float4 a = *(const float4*)&As[kk][ty * 4];
            float4 b = *(const float4*)&Bs[kk][tx * 4];
            acc[0][0] += a.x * b.x; acc[0][1] += a.x * b.y;
            acc[0][2] += a.x * b.z; acc[0][3] += a.x * b.w;
            acc[1][0] += a.y * b.x; acc[1][1] += a.y * b.y;
            acc[1][2] += a.y * b.z; acc[1][3] += a.y * b.w;
            acc[2][0] += a.z * b.x; acc[2][1] += a.z * b.y;
            acc[2][2] += a.z * b.z; acc[2][3] += a.z * b.w;
            acc[3][0] += a.w * b.x; acc[3][1] += a.w * b.y;
            acc[3][2] += a.w * b.z; acc[3][3] += a.w * b.w;
        }
        __syncthreads();
    }

    #pragma unroll
    for (int i = 0; i < 4; i++) {
        int m = m0 + ty * 4 + i;
        #pragma unroll
        for (int jj = 0; jj < 4; jj++) {
            int n = n0 + tx * 4 + jj;
            out[(size_t)m * N + n] = acc[i][jj] + bias[n];
        }
    }
}

// --------------------------- LSTM recurrence --------------------------------
// Thread map: tid = unit_local*8 + k. Thread (unit,k) owns h K-chunk k
// (32 floats) for ALL 4 gates of its unit (4x32 = 128 weights in regs).
// Per step: 8 rotated LDS.128 (bank-conflict-free), 64 FFMA2 into 4 gate
// partials, width-8 butterfly, lane-split MUFU tanh activation, width-8
// gather, redundant cell update, register-direct st.async exchange.
// Synchronization: 4-deep mbarrier ring, expect_tx for step t+2 posted
// (with its proxy fence) BEFORE the wait at step t, so the fence overlaps
// the wait stall. Ordering: on tid0, expect(t+2) -> fence -> st.async h(t);
// any h(t+2) arrival transitively requires a remote wait(t+1), which needs
// our h(t+1) stores, which follow tid0's h(t) store. Barrier (t+2)&3's
// previous phase (t-2) completed during step t-1's wait. hbuf WAR (2-deep)
// is safe: h(t+2) arrivals need all our h(t+1) stores, each of which
// depends on its group's reads of hbuf[(t+1)^1 & 1] = hbuf[t&1].
__global__ void __cluster_dims__(CSZ, 1, 1) __launch_bounds__(256, 1)
lstm_layer_kernel(const float* __restrict__ pre_f, const float* __restrict__ pre_b,
                  const float* __restrict__ Whh_f, const float* __restrict__ Whh_b,
                  float* __restrict__ out, int ostride)
{
    __shared__ __align__(16) float hbuf[2][HID];
    __shared__ __align__(8)  uint64_t mbar_store[4];

    int tid  = threadIdx.x;
    int rank = blockIdx.x & (CSZ - 1);
    int dir  = blockIdx.x / CSZ;

    const float* pre = dir ? pre_b : pre_f;
    const float* Whh = dir ? Whh_b : Whh_f;
    int off = dir ? HID : 0;

    int unit = tid >> 3;                 // 0..31 local unit
    int k    = tid & 7;                  // lane within unit group = K chunk
    int u    = rank * 32 + unit;         // global hidden unit
    int myg  = k & 3;                    // gate this lane activates

    uint32_t mb_base = smem_u32(&mbar_store[0]);
    uint32_t hb      = smem_u32(&hbuf[0][0]);

    // Weights: w2[g][j] = 16B line of gate-g row at K offset k*32 + rot(j)*4,
    // rot(j) = (j+k)&7 — matches the rotated h line loaded at step j.
    ulonglong2 w2[4][8];
    #pragma unroll
    for (int g = 0; g < 4; g++) {
        const float* wrow = Whh + (size_t)(g * HID + u) * HID + k * 32;
        #pragma unroll
        for (int j = 0; j < 8; j++) {
            int rot = (j + k) & 7;
            w2[g][j] = *(const ulonglong2*)(wrow + rot * 4);
        }
    }

    // remote addresses for my h pushes (to rank k): h by parity, mbar ring base
    uint32_t r_h0  = mapa_u32(hb + (uint32_t)u * 4u, (uint32_t)k);
    uint32_t r_h1  = r_h0 + (uint32_t)HID * 4u;
    uint32_t r_mbb = mapa_u32(mb_base, (uint32_t)k);

    // init: zero BOTH parity buffers (t=0 reads hbuf[1] as h(-1))
    hbuf[0][tid] = 0.f;
    hbuf[1][tid] = 0.f;
    if (tid < 4) mbar_init(mb_base + tid * 8u, 1);
    __syncthreads();
    if (tid == 0) {
        mbar_expect_tx(mb_base + 0u, HID * 4);   // expect h(0)
        mbar_expect_tx(mb_base + 8u, HID * 4);   // expect h(1)
    }
    CLUSTER_SYNC();                      // inits + expects visible cluster-wide

    float c = 0.f;
    // pre row for gate k (lanes k<4 carry it; k>=4 contribute 0)
    int tt0 = dir ? (TLEN - 1) : 0;
    float pv = (k < 4) ? __ldg(&pre[tt0 * 1024 + k * HID + u]) : 0.f;

    for (int t = 0; t < TLEN; t++) {
        // prefetch pre for t+1 BEFORE the wait (max slack, off critical path)
        float pv_next = 0.f;
        if (t + 1 < TLEN && k < 4) {
            int tt1 = dir ? (TLEN - 2 - t) : (t + 1);
            pv_next = __ldg(&pre[tt1 * 1024 + k * HID + u]);
        }

        // post expect for h(t+2) + proxy fence BEFORE the wait: the fence
        // latency overlaps the wait stall, and program order still puts it
        // before tid0's h(t) st.async (which gates all h(t+2) arrivals).
        if (t + 2 < TLEN && tid == 0) {
            mbar_expect_tx(mb_base + (uint32_t)((t + 2) & 3) * 8u, HID * 4);
            asm volatile("fence.proxy.async.shared::cta;" ::: "memory");
        }

        if (t > 0) {
            int tm = t - 1;   // wait h(t-1): mbar[tm&3], parity (tm>>2)&1
            mbar_wait_cluster(mb_base + (uint32_t)(tm & 3) * 8u,
                              (uint32_t)((tm >> 2) & 1));
        }

        int q  = t & 1;        // hbuf receiving h(t)
        int qp = q ^ 1;        // hbuf holding h(t-1)

        // 8 rotated LDS.128 of my 32-float chunk; 4 gate partials via FFMA2
        const char* hbase = (const char*)&hbuf[qp][k * 32];
        unsigned long long a0[4] = {0ull, 0ull, 0ull, 0ull};
        unsigned long long a1[4] = {0ull, 0ull, 0ull, 0ull};
        #pragma unroll
        for (int j = 0; j < 8; j++) {
            int rot = (j + k) & 7;
            ulonglong2 hv = *(const ulonglong2*)(hbase + rot * 16);
            #pragma unroll
            for (int g = 0; g < 4; g++) {
                asm("fma.rn.f32x2 %0, %1, %2, %0;"
                    : "+l"(a0[g]) : "l"(w2[g][j].x), "l"(hv.x));
                asm("fma.rn.f32x2 %0, %1, %2, %0;"
                    : "+l"(a1[g]) : "l"(w2[g][j].y), "l"(hv.y));
            }
        }
        // collapse packed accumulators -> 4 scalar partials; fold pre in the
        // lane that owns that gate's pre value (k<4, gate k)
        float s[4];
        #pragma unroll
        for (int g = 0; g < 4; g++) {
            float lo0 = __uint_as_float((unsigned)(a0[g] & 0xffffffffull));
            float hi0 = __uint_as_float((unsigned)(a0[g] >> 32));
            float lo1 = __uint_as_float((unsigned)(a1[g] & 0xffffffffull));
            float hi1 = __uint_as_float((unsigned)(a1[g] >> 32));
            s[g] = (lo0 + hi0) + (lo1 + hi1);
            s[g] += (k == g) ? pv : 0.f;
        }
        // width-8 butterfly: all lanes end with full sums of all 4 gates
        #pragma unroll
        for (int m = 1; m < 8; m <<= 1) {
            #pragma unroll
            for (int g = 0; g < 4; g++)
                s[g] += __shfl_xor_sync(0xffffffffu, s[g], m, 8);
        }

        // lane-split activation via MUFU tanh:
        //   gates i,f,o: sigmoid(x) = 0.5 + 0.5*tanh(x/2);  gate 2: tanh(x)
        float x   = (myg == 0) ? s[0] : (myg == 1) ? s[1]
                  : (myg == 2) ? s[2] : s[3];
        float z   = (myg == 2) ? x : 0.5f * x;
        float tz  = tanh_mufu(z);
        float act = (myg == 2) ? tz : fmaf(0.5f, tz, 0.5f);

        // gather the 4 activated gates (from lanes 0..3 of the group)
        float ai = __shfl_sync(0xffffffffu, act, 0, 8);
        float af = __shfl_sync(0xffffffffu, act, 1, 8);
        float ag = __shfl_sync(0xffffffffu, act, 2, 8);
        float ao = __shfl_sync(0xffffffffu, act, 3, 8);

        // redundant (deterministic) cell update in all 8 lanes
        c = af * c + ai * ag;
        float h = ao * tanh_mufu(c);

        int tt = dir ? (TLEN - 1 - t) : t;
        if (k == 0) out[(size_t)tt * ostride + off + u] = h;

        if (t + 1 < TLEN) {
            // push h to rank k's hbuf[q] + signal its ring mbar[t&3]
            st_async_f32(q ? r_h1 : r_h0, h, r_mbb + (uint32_t)(t & 3) * 8u);
        }
        pv = pv_next;
    }
    // no remote traffic after the final wait -> safe to exit without sync
}

// ------------------------------ heads --------------------------------------
__global__ __launch_bounds__(256) void heads_kernel(
    const float* __restrict__ x2, const float* __restrict__ Wm,
    float* __restrict__ sh, float* __restrict__ sd)
{
    int warp = threadIdx.x >> 5, lane = threadIdx.x & 31;
    int row = blockIdx.x * 8 + warp;
    const float4* xr = (const float4*)(x2 + (size_t)row * 512);
    const float4* wh = (const float4*)(Wm);
    const float4* wd = (const float4*)(Wm + 512);
    float a = 0.f, b = 0.f;
    #pragma unroll 4
    for (int i = lane; i < 128; i += 32) {
        float4 xv = xr[i]; float4 hv = wh[i]; float4 dv = wd[i];
        a += xv.x * hv.x + xv.y * hv.y + xv.z * hv.z + xv.w * hv.w;
        b += xv.x * dv.x + xv.y * dv.y + xv.z * dv.z + xv.w * dv.w;
    }
    #pragma unroll
    for (int o = 16; o; o >>= 1) {
        a += __shfl_xor_sync(0xffffffffu, a, o);
        b += __shfl_xor_sync(0xffffffffu, b, o);
    }
    if (lane == 0) { sh[row] = a; sd[row] = b; }
}

// ------------------------------ scores -------------------------------------
__global__ __launch_bounds__(256) void scores_kernel(
    const float* __restrict__ sh, const float* __restrict__ sd,
    const float* __restrict__ bm, float* __restrict__ out)
{
    float bb = __ldg(bm);
    size_t nquad = (size_t)TLEN * TLEN / 4;
    size_t stride = (size_t)gridDim.x * blockDim.x;
    for (size_t idx = (size_t)blockIdx.x * blockDim.x + threadIdx.x;
         idx < nquad; idx += stride) {
        int i  = (int)(idx >> 9);           // row (2048/4 = 512 quads per row)
        int j0 = (int)((idx & 511) << 2);   // first col of quad
        float si = sh[i];
        float4 r;
        r.x = (j0 + 0 > i) ? tanhf(si + sd[j0 + 0] + bb) : 0.f;
        r.y = (j0 + 1 > i) ? tanhf(si + sd[j0 + 1] + bb) : 0.f;
        r.z = (j0 + 2 > i) ? tanhf(si + sd[j0 + 2] + bb) : 0.f;
        r.w = (j0 + 3 > i) ? tanhf(si + sd[j0 + 3] + bb) : 0.f;
        *(float4*)(out + ((size_t)i * TLEN + j0)) = r;
    }
}

// ------------------------------ launch -------------------------------------
extern "C" void kernel_launch(void* const* d_in, const int* in_sizes, int n_in,
                              void* d_out, int out_size)
{
    const int*   word_idx = (const int*)  d_in[0];
    const float* E        = (const float*)d_in[1];
    const float* Wih0f    = (const float*)d_in[2];
    const float* Whh0f    = (const float*)d_in[3];
    const float* b0f      = (const float*)d_in[4];
    const float* Wih0b    = (const float*)d_in[5];
    const float* Whh0b    = (const float*)d_in[6];
    const float* b0b      = (const float*)d_in[7];
    const float* Wih1f    = (const float*)d_in[8];
    const float* Whh1f    = (const float*)d_in[9];
    const float* b1f      = (const float*)d_in[10];
    const float* Wih1b    = (const float*)d_in[11];
    const float* Whh1b    = (const float*)d_in[12];
    const float* b1b      = (const float*)d_in[13];
    const float* Wm       = (const float*)d_in[14];
    const float* bm       = (const float*)d_in[15];
    float* out = (float*)d_out;

    float *pre0f, *pre0b, *pre1f, *pre1b, *x1, *x2, *sh, *sd;
    cudaGetSymbolAddress((void**)&pre0f, g_pre0f);
    cudaGetSymbolAddress((void**)&pre0b, g_pre0b);
    cudaGetSymbolAddress((void**)&pre1f, g_pre1f);
    cudaGetSymbolAddress((void**)&pre1b, g_pre1b);
    cudaGetSymbolAddress((void**)&x1,    g_x1);
    cudaGetSymbolAddress((void**)&x2,    g_x2);
    cudaGetSymbolAddress((void**)&sh,    g_sh);
    cudaGetSymbolAddress((void**)&sd,    g_sd);

    dim3 gg(1024 / BN, TLEN / BM, 2);

    // layer 0 input projection (both directions, fused embedding gather)
    gemm_bias2_kernel<<<gg, 256>>>(nullptr, word_idx, E,
                                   Wih0f, b0f, pre0f, Wih0b, b0b, pre0b,
                                   TLEN, 1024, 256);
    // layer 0 recurrence (fwd + bwd clusters)
    lstm_layer_kernel<<<2 * CSZ, 256>>>(pre0f, pre0b, Whh0f, Whh0b, x1, 512);

    // layer 1 input projection
    gemm_bias2_kernel<<<gg, 256>>>(x1, nullptr, nullptr,
                                   Wih1f, b1f, pre1f, Wih1b, b1b, pre1b,
                                   TLEN, 1024, 512);
    // layer 1 recurrence
    lstm_layer_kernel<<<2 * CSZ, 256>>>(pre1f, pre1b, Whh1f, Whh1b, x2, 512);

    // scoring head
    heads_kernel<<<TLEN / 8, 256>>>(x2, Wm, sh, sd);
    scores_kernel<<<2048, 256>>>(sh, sd, bm, out);
}

// round 16
// speedup vs baseline: 2.8305x; 1.0128x over previous
#include <cuda_runtime.h>
#include <cuda_bf16.h>
#include <cstdint>
#include <cstddef>

// ---------------------------------------------------------------------------
// DependencyParsingNetwork: embed -> 2-layer biLSTM (T=2048, H=256) -> masked
// tanh score matrix [T,T].
//
//   1. gemm_bias2: pre0{f,b} = gather(E,idx) @ Wih0{f,b}^T + b    (one launch)
//      128x128x8 double-buffered tiles, 8x8 register tile (split 2x2 of 4x4).
//   2. lstm_layer: cluster of 8 CTAs per direction. Thread (unit,k) owns
//      K-chunk k for all 4 gates: 8 rotated bank-conflict-free LDS.128,
//      64 FFMA2, width-8 butterfly, lane-split MUFU tanh activations.
//      h exchanged via register-direct st.async + 4-deep mbarrier ring;
//      expect_tx posted 2 steps ahead; no per-step __syncthreads.
//      (UNCHANGED from the 2765us round — do not touch.)
//   3. gemm_bias2: pre1{f,b} = x1 @ Wih1{f,b}^T + b
//   4. lstm_layer -> x2
//   5. heads + masked MUFU-tanh scores
// ---------------------------------------------------------------------------

#define TLEN 2048
#define HID  256
#define CSZ  8      // cluster size (CTAs per direction)

// ------------------------- device scratch (static) -------------------------
__device__ float g_pre0f[TLEN * 1024];
__device__ float g_pre0b[TLEN * 1024];
__device__ float g_pre1f[TLEN * 1024];
__device__ float g_pre1b[TLEN * 1024];
__device__ float g_x1[TLEN * 512];
__device__ float g_x2[TLEN * 512];
__device__ float g_sh[TLEN];
__device__ float g_sd[TLEN];

// ------------------------------ helpers ------------------------------------
__device__ __forceinline__ uint32_t smem_u32(const void* p) {
    uint32_t a;
    asm("{ .reg .u64 t; cvta.to.shared.u64 t, %1; cvt.u32.u64 %0, t; }"
        : "=r"(a) : "l"(p));
    return a;
}

#define CLUSTER_SYNC() do { \
    asm volatile("barrier.cluster.arrive.aligned;" ::: "memory"); \
    asm volatile("barrier.cluster.wait.aligned;" ::: "memory"); \
} while (0)

__device__ __forceinline__ void mbar_init(uint32_t mbar, uint32_t count) {
    asm volatile("mbarrier.init.shared.b64 [%0], %1;" :: "r"(mbar), "r"(count)
                 : "memory");
}
__device__ __forceinline__ void mbar_expect_tx(uint32_t mbar, uint32_t bytes) {
    asm volatile("mbarrier.arrive.expect_tx.shared.b64 _, [%0], %1;"
                 :: "r"(mbar), "r"(bytes) : "memory");
}
// acquire at cluster scope: data was produced by remote-CTA st.async
__device__ __forceinline__ void mbar_wait_cluster(uint32_t mbar, uint32_t parity) {
    uint32_t done;
    asm volatile(
        "{\n\t.reg .pred p;\n\t"
        "mbarrier.try_wait.parity.acquire.cluster.shared::cta.b64 p, [%1], %2;\n\t"
        "selp.b32 %0, 1, 0, p;\n\t}"
        : "=r"(done) : "r"(mbar), "r"(parity) : "memory");
    while (!done) {
        asm volatile(
            "{\n\t.reg .pred p;\n\t"
            "mbarrier.try_wait.parity.acquire.cluster.shared::cta.b64 p, [%1], %2, 0x989680;\n\t"
            "selp.b32 %0, 1, 0, p;\n\t}"
            : "=r"(done) : "r"(mbar), "r"(parity) : "memory");
    }
}
__device__ __forceinline__ uint32_t mapa_u32(uint32_t laddr, uint32_t rank) {
    uint32_t r;
    asm volatile("mapa.shared::cluster.u32 %0, %1, %2;"
                 : "=r"(r) : "r"(laddr), "r"(rank));
    return r;
}
// remote smem store with tx-count completion on remote mbarrier
__device__ __forceinline__ void st_async_f32(uint32_t raddr, float v, uint32_t rbar) {
    asm volatile(
        "st.async.shared::cluster.mbarrier::complete_tx::bytes.b32 [%0], %1, [%2];"
        :: "r"(raddr), "r"(__float_as_uint(v)), "r"(rbar) : "memory");
}

// MUFU tanh: single-instruction approx (rel err ~5e-4).
__device__ __forceinline__ float tanh_mufu(float x) {
    float y;
    asm("tanh.approx.f32 %0, %1;" : "=f"(y) : "f"(x));
    return y;
}

// ------------------------------ GEMM ---------------------------------------
// out{0,1}[M,N] = A[M,K] @ W{0,1}[N,K]^T + bias{0,1}[N]; z selects direction.
// 128x128 block, BK=8, 256 threads, 8x8 register tile (2x2 blocks of 4x4 at
// +0/+64 split — conflict-free quarter-warp LDS), double-buffered smem.
#define BM 128
#define BN 128
#define BK 8
#define GP 4

__global__ __launch_bounds__(256) void gemm_bias2_kernel(
    const float* __restrict__ X, const int* __restrict__ idx,
    const float* __restrict__ E,
    const float* __restrict__ W0, const float* __restrict__ bias0,
    float* __restrict__ out0,
    const float* __restrict__ W1, const float* __restrict__ bias1,
    float* __restrict__ out1,
    int M, int N, int K)
{
    __shared__ __align__(16) float As[2][BK][BM + GP];
    __shared__ __align__(16) float Bs[2][BK][BN + GP];

    const float* W    = blockIdx.z ? W1    : W0;
    const float* bias = blockIdx.z ? bias1 : bias0;
    float*       out  = blockIdx.z ? out1  : out0;

    int tid  = threadIdx.x;
    int m0   = blockIdx.y * BM, n0 = blockIdx.x * BN;
    int lrow = tid >> 1;            // 0..127
    int lcol = (tid & 1) * 4;       // 0 or 4
    int tx   = tid & 15;            // 0..15
    int ty   = tid >> 4;            // 0..15

    const float* Arow;
    if (idx) Arow = E + (size_t)idx[m0 + lrow] * K;
    else     Arow = X + (size_t)(m0 + lrow) * K;
    const float* Brow = W + (size_t)(n0 + lrow) * K;

    // stage 0
    {
        float4 a = *(const float4*)(Arow + lcol);
        float4 b = *(const float4*)(Brow + lcol);
        As[0][lcol + 0][lrow] = a.x; As[0][lcol + 1][lrow] = a.y;
        As[0][lcol + 2][lrow] = a.z; As[0][lcol + 3][lrow] = a.w;
        Bs[0][lcol + 0][lrow] = b.x; Bs[0][lcol + 1][lrow] = b.y;
        Bs[0][lcol + 2][lrow] = b.z; Bs[0][lcol + 3][lrow] = b.w;
    }
    __syncthreads();

    float acc[8][8] = {};
    int nkb = K / BK;
    int cur = 0;

    for (int kb = 0; kb < nkb; kb++) {
        float4 an, bn;
        bool more = (kb + 1 < nkb);
        if (more) {
            an = *(const float4*)(Arow + (kb + 1) * BK + lcol);
            bn = *(const float4*)(Brow + (kb + 1) * BK + lcol);
        }

        #pragma unroll
        for (int kk = 0; kk < BK; kk++) {
            float4 a0 = *(const float4*)&As[cur][kk][ty * 4];
            float4 a1 = *(const float4*)&As[cur][kk][ty * 4 + 64];
            float4 b0 = *(const float4*)&Bs[cur][kk][tx * 4];
            float4 b1 = *(const float4*)&Bs[cur][kk][tx * 4 + 64];
            float ar[8] = {a0.x, a0.y, a0.z, a0.w, a1.x, a1.y, a1.z, a1.w};
            float br[8] = {b0.x, b0.y, b0.z, b0.w, b1.x, b1.y, b1.z, b1.w};
            #pragma unroll
            for (int i = 0; i < 8; i++)
                #pragma unroll
                for (int j = 0; j < 8; j++)
                    acc[i][j] += ar[i] * br[j];
        }

        if (more) {
            int nxt = cur ^ 1;
            As[nxt][lcol + 0][lrow] = an.x; As[nxt][lcol + 1][lrow] = an.y;
            As[nxt][lcol + 2][lrow] = an.z; As[nxt][lcol + 3][lrow] = an.w;
            Bs[nxt][lcol + 0][lrow] = bn.x; Bs[nxt][lcol + 1][lrow] = bn.y;
            Bs[nxt][lcol + 2][lrow] = bn.z; Bs[nxt][lcol + 3][lrow] = bn.w;
            __syncthreads();
            cur = nxt;
        }
    }

    // epilogue: rows {ty*4+i, ty*4+64+i}, cols {tx*4+j, tx*4+64+j}
    float bv[8];
    #pragma unroll
    for (int j = 0; j < 8; j++)
        bv[j] = bias[n0 + tx * 4 + (j & 3) + (j >> 2) * 64];

    #pragma unroll
    for (int i = 0; i < 8; i++) {
        int m = m0 + ty * 4 + (i & 3) + (i >> 2) * 64;
        float4 r0, r1;
        r0.x = acc[i][0] + bv[0]; r0.y = acc[i][1] + bv[1];
        r0.z = acc[i][2] + bv[2]; r0.w = acc[i][3] + bv[3];
        r1.x = acc[i][4] + bv[4]; r1.y = acc[i][5] + bv[5];
        r1.z = acc[i][6] + bv[6]; r1.w = acc[i][7] + bv[7];
        *(float4*)(out + (size_t)m * N + n0 + tx * 4)      = r0;
        *(float4*)(out + (size_t)m * N + n0 + tx * 4 + 64) = r1;
    }
}

// --------------------------- LSTM recurrence --------------------------------
// (byte-identical to the 2765us round — proven; do not modify)
__global__ void __cluster_dims__(CSZ, 1, 1) __launch_bounds__(256, 1)
lstm_layer_kernel(const float* __restrict__ pre_f, const float* __restrict__ pre_b,
                  const float* __restrict__ Whh_f, const float* __restrict__ Whh_b,
                  float* __restrict__ out, int ostride)
{
    __shared__ __align__(16) float hbuf[2][HID];
    __shared__ __align__(8)  uint64_t mbar_store[4];

    int tid  = threadIdx.x;
    int rank = blockIdx.x & (CSZ - 1);
    int dir  = blockIdx.x / CSZ;

    const float* pre = dir ? pre_b : pre_f;
    const float* Whh = dir ? Whh_b : Whh_f;
    int off = dir ? HID : 0;

    int unit = tid >> 3;                 // 0..31 local unit
    int k    = tid & 7;                  // lane within unit group = K chunk
    int u    = rank * 32 + unit;         // global hidden unit
    int myg  = k & 3;                    // gate this lane activates

    uint32_t mb_base = smem_u32(&mbar_store[0]);
    uint32_t hb      = smem_u32(&hbuf[0][0]);

    ulonglong2 w2[4][8];
    #pragma unroll
    for (int g = 0; g < 4; g++) {
        const float* wrow = Whh + (size_t)(g * HID + u) * HID + k * 32;
        #pragma unroll
        for (int j = 0; j < 8; j++) {
            int rot = (j + k) & 7;
            w2[g][j] = *(const ulonglong2*)(wrow + rot * 4);
        }
    }

    uint32_t r_h0  = mapa_u32(hb + (uint32_t)u * 4u, (uint32_t)k);
    uint32_t r_h1  = r_h0 + (uint32_t)HID * 4u;
    uint32_t r_mbb = mapa_u32(mb_base, (uint32_t)k);

    hbuf[0][tid] = 0.f;
    hbuf[1][tid] = 0.f;
    if (tid < 4) mbar_init(mb_base + tid * 8u, 1);
    __syncthreads();
    if (tid == 0) {
        mbar_expect_tx(mb_base + 0u, HID * 4);   // expect h(0)
        mbar_expect_tx(mb_base + 8u, HID * 4);   // expect h(1)
    }
    CLUSTER_SYNC();

    float c = 0.f;
    int tt0 = dir ? (TLEN - 1) : 0;
    float pv = (k < 4) ? __ldg(&pre[tt0 * 1024 + k * HID + u]) : 0.f;

    for (int t = 0; t < TLEN; t++) {
        float pv_next = 0.f;
        if (t + 1 < TLEN && k < 4) {
            int tt1 = dir ? (TLEN - 2 - t) : (t + 1);
            pv_next = __ldg(&pre[tt1 * 1024 + k * HID + u]);
        }

        if (t + 2 < TLEN && tid == 0) {
            mbar_expect_tx(mb_base + (uint32_t)((t + 2) & 3) * 8u, HID * 4);
            asm volatile("fence.proxy.async.shared::cta;" ::: "memory");
        }

        if (t > 0) {
            int tm = t - 1;
            mbar_wait_cluster(mb_base + (uint32_t)(tm & 3) * 8u,
                              (uint32_t)((tm >> 2) & 1));
        }

        int q  = t & 1;
        int qp = q ^ 1;

        const char* hbase = (const char*)&hbuf[qp][k * 32];
        unsigned long long a0[4] = {0ull, 0ull, 0ull, 0ull};
        unsigned long long a1[4] = {0ull, 0ull, 0ull, 0ull};
        #pragma unroll
        for (int j = 0; j < 8; j++) {
            int rot = (j + k) & 7;
            ulonglong2 hv = *(const ulonglong2*)(hbase + rot * 16);
            #pragma unroll
            for (int g = 0; g < 4; g++) {
                asm("fma.rn.f32x2 %0, %1, %2, %0;"
                    : "+l"(a0[g]) : "l"(w2[g][j].x), "l"(hv.x));
                asm("fma.rn.f32x2 %0, %1, %2, %0;"
                    : "+l"(a1[g]) : "l"(w2[g][j].y), "l"(hv.y));
            }
        }
        float s[4];
        #pragma unroll
        for (int g = 0; g < 4; g++) {
            float lo0 = __uint_as_float((unsigned)(a0[g] & 0xffffffffull));
            float hi0 = __uint_as_float((unsigned)(a0[g] >> 32));
            float lo1 = __uint_as_float((unsigned)(a1[g] & 0xffffffffull));
            float hi1 = __uint_as_float((unsigned)(a1[g] >> 32));
            s[g] = (lo0 + hi0) + (lo1 + hi1);
            s[g] += (k == g) ? pv : 0.f;
        }
        #pragma unroll
        for (int m = 1; m < 8; m <<= 1) {
            #pragma unroll
            for (int g = 0; g < 4; g++)
                s[g] += __shfl_xor_sync(0xffffffffu, s[g], m, 8);
        }

        float x   = (myg == 0) ? s[0] : (myg == 1) ? s[1]
                  : (myg == 2) ? s[2] : s[3];
        float z   = (myg == 2) ? x : 0.5f * x;
        float tz  = tanh_mufu(z);
        float act = (myg == 2) ? tz : fmaf(0.5f, tz, 0.5f);

        float ai = __shfl_sync(0xffffffffu, act, 0, 8);
        float af = __shfl_sync(0xffffffffu, act, 1, 8);
        float ag = __shfl_sync(0xffffffffu, act, 2, 8);
        float ao = __shfl_sync(0xffffffffu, act, 3, 8);

        c = af * c + ai * ag;
        float h = ao * tanh_mufu(c);

        int tt = dir ? (TLEN - 1 - t) : t;
        if (k == 0) out[(size_t)tt * ostride + off + u] = h;

        if (t + 1 < TLEN) {
            st_async_f32(q ? r_h1 : r_h0, h, r_mbb + (uint32_t)(t & 3) * 8u);
        }
        pv = pv_next;
    }
}

// ------------------------------ heads --------------------------------------
__global__ __launch_bounds__(256) void heads_kernel(
    const float* __restrict__ x2, const float* __restrict__ Wm,
    float* __restrict__ sh, float* __restrict__ sd)
{
    int warp = threadIdx.x >> 5, lane = threadIdx.x & 31;
    int row = blockIdx.x * 8 + warp;
    const float4* xr = (const float4*)(x2 + (size_t)row * 512);
    const float4* wh = (const float4*)(Wm);
    const float4* wd = (const float4*)(Wm + 512);
    float a = 0.f, b = 0.f;
    #pragma unroll 4
    for (int i = lane; i < 128; i += 32) {
        float4 xv = xr[i]; float4 hv = wh[i]; float4 dv = wd[i];
        a += xv.x * hv.x + xv.y * hv.y + xv.z * hv.z + xv.w * hv.w;
        b += xv.x * dv.x + xv.y * dv.y + xv.z * dv.z + xv.w * dv.w;
    }
    #pragma unroll
    for (int o = 16; o; o >>= 1) {
        a += __shfl_xor_sync(0xffffffffu, a, o);
        b += __shfl_xor_sync(0xffffffffu, b, o);
    }
    if (lane == 0) { sh[row] = a; sd[row] = b; }
}

// ------------------------------ scores -------------------------------------
__global__ __launch_bounds__(256) void scores_kernel(
    const float* __restrict__ sh, const float* __restrict__ sd,
    const float* __restrict__ bm, float* __restrict__ out)
{
    float bb = __ldg(bm);
    size_t nquad = (size_t)TLEN * TLEN / 4;
    size_t stride = (size_t)gridDim.x * blockDim.x;
    for (size_t idx = (size_t)blockIdx.x * blockDim.x + threadIdx.x;
         idx < nquad; idx += stride) {
        int i  = (int)(idx >> 9);           // row (2048/4 = 512 quads per row)
        int j0 = (int)((idx & 511) << 2);   // first col of quad
        float si = sh[i];
        float4 r;
        r.x = (j0 + 0 > i) ? tanh_mufu(si + sd[j0 + 0] + bb) : 0.f;
        r.y = (j0 + 1 > i) ? tanh_mufu(si + sd[j0 + 1] + bb) : 0.f;
        r.z = (j0 + 2 > i) ? tanh_mufu(si + sd[j0 + 2] + bb) : 0.f;
        r.w = (j0 + 3 > i) ? tanh_mufu(si + sd[j0 + 3] + bb) : 0.f;
        *(float4*)(out + ((size_t)i * TLEN + j0)) = r;
    }
}

// ------------------------------ launch -------------------------------------
extern "C" void kernel_launch(void* const* d_in, const int* in_sizes, int n_in,
                              void* d_out, int out_size)
{
    const int*   word_idx = (const int*)  d_in[0];
    const float* E        = (const float*)d_in[1];
    const float* Wih0f    = (const float*)d_in[2];
    const float* Whh0f    = (const float*)d_in[3];
    const float* b0f      = (const float*)d_in[4];
    const float* Wih0b    = (const float*)d_in[5];
    const float* Whh0b    = (const float*)d_in[6];
    const float* b0b      = (const float*)d_in[7];
    const float* Wih1f    = (const float*)d_in[8];
    const float* Whh1f    = (const float*)d_in[9];
    const float* b1f      = (const float*)d_in[10];
    const float* Wih1b    = (const float*)d_in[11];
    const float* Whh1b    = (const float*)d_in[12];
    const float* b1b      = (const float*)d_in[13];
    const float* Wm       = (const float*)d_in[14];
    const float* bm       = (const float*)d_in[15];
    float* out = (float*)d_out;

    float *pre0f, *pre0b, *pre1f, *pre1b, *x1, *x2, *sh, *sd;
    cudaGetSymbolAddress((void**)&pre0f, g_pre0f);
    cudaGetSymbolAddress((void**)&pre0b, g_pre0b);
    cudaGetSymbolAddress((void**)&pre1f, g_pre1f);
    cudaGetSymbolAddress((void**)&pre1b, g_pre1b);
    cudaGetSymbolAddress((void**)&x1,    g_x1);
    cudaGetSymbolAddress((void**)&x2,    g_x2);
    cudaGetSymbolAddress((void**)&sh,    g_sh);
    cudaGetSymbolAddress((void**)&sd,    g_sd);

    dim3 gg(1024 / BN, TLEN / BM, 2);

    // layer 0 input projection (both directions, fused embedding gather)
    gemm_bias2_kernel<<<gg, 256>>>(nullptr, word_idx, E,
                                   Wih0f, b0f, pre0f, Wih0b, b0b, pre0b,
                                   TLEN, 1024, 256);
    // layer 0 recurrence (fwd + bwd clusters)
    lstm_layer_kernel<<<2 * CSZ, 256>>>(pre0f, pre0b, Whh0f, Whh0b, x1, 512);

    // layer 1 input projection
    gemm_bias2_kernel<<<gg, 256>>>(x1, nullptr, nullptr,
                                   Wih1f, b1f, pre1f, Wih1b, b1b, pre1b,
                                   TLEN, 1024, 512);
    // layer 1 recurrence
    lstm_layer_kernel<<<2 * CSZ, 256>>>(pre1f, pre1b, Whh1f, Whh1b, x2, 512);

    // scoring head
    heads_kernel<<<TLEN / 8, 256>>>(x2, Wm, sh, sd);
    scores_kernel<<<2048, 256>>>(sh, sd, bm, out);
}